// round 4
// baseline (speedup 1.0000x reference)
#include <cuda_runtime.h>
#include <math.h>

#define PI_F 3.14159265358979323846f

#define GG   16   // o*4 + b  (4 output chains x 4 batch)
#define CC   32   // width
#define HH   256
#define WW   256
#define MM   16   // Fourier modes per dim
#define NPIX 65536

// ---- scratch (static device allocations; no cudaMalloc anywhere) ----
__device__ float g_x0[4 * CC * NPIX];            //  33.5 MB lifted input (shared by all o)
__device__ float g_A [GG * CC * NPIX];           // 134 MB ping
__device__ float g_B [GG * CC * NPIX];           // 134 MB pong
__device__ float g_XF[GG * CC * 256 * 2];        // fwd spectrum  [g][c][ky*16+kx]{re,im}
__device__ float g_YF[GG * CC * 256 * 2];        // mixed spectrum, same layout
__device__ float g_Z [GG * HH * CC * MM * 2];    // after inverse-h DFT: [g][h][c][kx]{re,im}
__device__ float g_wtR[16 * 256 * 1024];         // weights transposed: [o*4+n][ky*16+kx][i*32+c]
__device__ float g_wtI[16 * 256 * 1024];

// ======================= lift: conv1x1 (3 -> 32) =======================
__global__ void lift_kernel(const float* __restrict__ x,
                            const float* __restrict__ lw,
                            const float* __restrict__ lb)
{
    int idx = blockIdx.x * blockDim.x + threadIdx.x;
    if (idx >= 4 * CC * (NPIX / 4)) return;
    int p4 = idx % (NPIX / 4);
    int c  = (idx / (NPIX / 4)) % CC;
    int b  = idx / ((NPIX / 4) * CC);
    const float4* xb = (const float4*)(x + (size_t)b * 3 * NPIX);
    float4 v0 = xb[p4];
    float4 v1 = xb[p4 + NPIX / 4];
    float4 v2 = xb[p4 + NPIX / 2];
    float w0 = lw[c * 3 + 0], w1 = lw[c * 3 + 1], w2 = lw[c * 3 + 2], bv = lb[c];
    float4 r;
    r.x = bv + w0 * v0.x + w1 * v1.x + w2 * v2.x;
    r.y = bv + w0 * v0.y + w1 * v1.y + w2 * v2.y;
    r.z = bv + w0 * v0.z + w1 * v1.z + w2 * v2.z;
    r.w = bv + w0 * v0.w + w1 * v1.w + w2 * v2.w;
    ((float4*)g_x0)[(size_t)(b * CC + c) * (NPIX / 4) + p4] = r;
}

// ============ weight prep: transpose + fold ALL normalization ============
// out[(o*4+n)][ky*16+kx][i*32+c] = wr/wi[o][n][i][c][ky][kx] * c_kx / 65536
__global__ void wprep_kernel(const float* __restrict__ wr,
                             const float* __restrict__ wi)
{
    int idx = blockIdx.x * blockDim.x + threadIdx.x;
    if (idx >= 16 * 256 * 1024) return;
    int on = idx >> 18;            // / (256*1024)
    int r  = idx & 262143;
    int kk = r >> 10;
    int ic = r & 1023;
    int i  = ic >> 5;
    int c  = ic & 31;
    int kx = kk & 15;
    float s = (kx == 0 ? 1.0f : 2.0f) * (1.0f / 65536.0f);
    size_t in = ((size_t)(on * 32 + i) * 32 + c) * 256 + kk;
    g_wtR[idx] = wr[in] * s;
    g_wtI[idx] = wi[in] * s;
}

// ======================= K1: forward truncated 2-D DFT =======================
// Per block: one (g, c) channel image. Stage 1 (w->kx, radix-16 split) into smem,
// stage 2 (h->ky, incremental rotation) into register accumulators.
__global__ __launch_bounds__(256) void dft_fwd_kernel(const float* __restrict__ Xin, int bcast)
{
    int g   = blockIdx.x >> 5;
    int c   = blockIdx.x & 31;
    int gin = bcast ? (g & 3) : g;
    int t   = threadIdx.x;
    int kx  = t & 15;   // phase-1 kx AND phase-2 kx
    int hp  = t >> 4;   // phase-1 row-pair id
    int ky  = t >> 4;   // phase-2 ky

    __shared__ float sx[32 * 256];
    __shared__ float sT[32][16][2];

    // phase-1 twiddle tables (register resident, depend only on kx)
    float cwb[16], swb[16], cu[16], su[16];
#pragma unroll
    for (int b = 0; b < 16; b++) {
        int m1 = (kx * b) & 255;
        int m2 = (kx * b) & 15;
        float a1 = -2.0f * PI_F * (float)m1 * (1.0f / 256.0f);
        float a2 = -2.0f * PI_F * (float)m2 * (1.0f / 16.0f);
        sincosf(a1, &swb[b], &cwb[b]);
        sincosf(a2, &su[b], &cu[b]);
    }

    // phase-2 rotation step e^{-2*pi*i*ky/256}
    float cs2, ss2;
    sincosf(-2.0f * PI_F * (float)ky * (1.0f / 256.0f), &ss2, &cs2);
    float pr = 1.0f, pq = 0.0f;
    float accR = 0.0f, accI = 0.0f;

    const float* src = Xin + ((size_t)(gin * CC + c)) * NPIX;

    for (int tile = 0; tile < 8; tile++) {
        // load 32 rows (32 KB), fully coalesced float4
        const float4* s4 = (const float4*)(src + tile * 8192);
        float4* d4 = (float4*)sx;
#pragma unroll
        for (int j = 0; j < 8; j++) d4[t + j * 256] = s4[t + j * 256];
        __syncthreads();

        // ---- stage 1: row DFT along w (radix 16x16) ----
#pragma unroll
        for (int rr = 0; rr < 2; rr++) {
            int h = hp + rr * 16;
            const float4* xr4 = (const float4*)&sx[h * 256];
            float tr = 0.0f, ti = 0.0f;
#pragma unroll
            for (int a = 0; a < 16; a++) {
                float4 v0 = xr4[a * 4 + 0];
                float4 v1 = xr4[a * 4 + 1];
                float4 v2 = xr4[a * 4 + 2];
                float4 v3 = xr4[a * 4 + 3];
                float gr = v0.x*cwb[0] + v0.y*cwb[1] + v0.z*cwb[2] + v0.w*cwb[3]
                         + v1.x*cwb[4] + v1.y*cwb[5] + v1.z*cwb[6] + v1.w*cwb[7]
                         + v2.x*cwb[8] + v2.y*cwb[9] + v2.z*cwb[10]+ v2.w*cwb[11]
                         + v3.x*cwb[12]+ v3.y*cwb[13]+ v3.z*cwb[14]+ v3.w*cwb[15];
                float gi = v0.x*swb[0] + v0.y*swb[1] + v0.z*swb[2] + v0.w*swb[3]
                         + v1.x*swb[4] + v1.y*swb[5] + v1.z*swb[6] + v1.w*swb[7]
                         + v2.x*swb[8] + v2.y*swb[9] + v2.z*swb[10]+ v2.w*swb[11]
                         + v3.x*swb[12]+ v3.y*swb[13]+ v3.z*swb[14]+ v3.w*swb[15];
                tr += gr * cu[a] - gi * su[a];
                ti += gr * su[a] + gi * cu[a];
            }
            sT[h][kx][0] = tr;
            sT[h][kx][1] = ti;
        }
        __syncthreads();

        // ---- stage 2: accumulate over h with rotating phase ----
#pragma unroll
        for (int hl = 0; hl < 32; hl++) {
            float tr = sT[hl][kx][0];
            float ti = sT[hl][kx][1];
            accR += tr * pr - ti * pq;
            accI += tr * pq + ti * pr;
            float npr = pr * cs2 - pq * ss2;
            pq = pr * ss2 + pq * cs2;
            pr = npr;
        }
        __syncthreads();
    }

    ((float2*)g_XF)[(g * CC + c) * 256 + ky * 16 + kx] = make_float2(accR, accI);
}

// ======================= K2: spectral channel mixing =======================
__global__ void spectral_kernel(int n)
{
    int g  = blockIdx.x >> 8;
    int kk = blockIdx.x & 255;
    int c  = threadIdx.x;        // 32 threads
    int o  = g >> 2;

    __shared__ float sxf[64];    // XF[g][i][kk] complex, i=0..31
    ((float2*)sxf)[c] = ((const float2*)g_XF)[(g * CC + c) * 256 + kk];
    __syncwarp();

    const float* wR = g_wtR + ((size_t)((o * 4 + n) * 256 + kk)) * 1024 + c;
    const float* wI = g_wtI + ((size_t)((o * 4 + n) * 256 + kk)) * 1024 + c;

    float ar = 0.0f, ai = 0.0f;
#pragma unroll
    for (int i = 0; i < 32; i++) {
        float xr = sxf[2 * i], xi = sxf[2 * i + 1];
        float wrv = wR[i * 32], wiv = wI[i * 32];
        ar += xr * wrv - xi * wiv;
        ai += xr * wiv + xi * wrv;
    }
    ((float2*)g_YF)[(g * CC + c) * 256 + kk] = make_float2(ar, ai);
}

// ======================= K3: inverse DFT along h (ky -> h) =======================
__global__ __launch_bounds__(256) void dft_invh_kernel()
{
    int g = blockIdx.x >> 5;
    int c = blockIdx.x & 31;
    int h = threadIdx.x;

    __shared__ float sYF[512];   // [ky*16+kx]{re,im}
    ((float2*)sYF)[h] = ((const float2*)g_YF)[(g * CC + c) * 256 + h];
    __syncthreads();

    float accR[16], accI[16];
#pragma unroll
    for (int k = 0; k < 16; k++) { accR[k] = 0.0f; accI[k] = 0.0f; }

    float cs, ss;
    sincosf(2.0f * PI_F * (float)h * (1.0f / 256.0f), &ss, &cs);
    float pr = 1.0f, pq = 0.0f;       // e^{+2*pi*i*h*ky/256}

#pragma unroll
    for (int ky = 0; ky < 16; ky++) {
        const float4* y4 = (const float4*)&sYF[ky * 32];
#pragma unroll
        for (int q = 0; q < 8; q++) {
            float4 y = y4[q];
            int k0 = 2 * q, k1 = 2 * q + 1;
            accR[k0] += y.x * pr - y.y * pq;
            accI[k0] += y.x * pq + y.y * pr;
            accR[k1] += y.z * pr - y.w * pq;
            accI[k1] += y.z * pq + y.w * pr;
        }
        float npr = pr * cs - pq * ss;
        pq = pr * ss + pq * cs;
        pr = npr;
    }

    float4* zdst = (float4*)(g_Z + ((size_t)(g * 256 + h) * CC + c) * 32);
#pragma unroll
    for (int q = 0; q < 8; q++)
        zdst[q] = make_float4(accR[2 * q], accI[2 * q], accR[2 * q + 1], accI[2 * q + 1]);
}

// ===== K4: inverse DFT along w + bypass conv1x1 + exact gelu (+ fused proj) =====
__global__ __launch_bounds__(256) void finish_kernel(const float* __restrict__ Xin,
                                                     float* __restrict__ Xout,
                                                     const float* __restrict__ bw,
                                                     const float* __restrict__ bb,
                                                     const float* __restrict__ pw,
                                                     const float* __restrict__ pb,
                                                     float* __restrict__ out,
                                                     int n, int bcast, int last)
{
    int g   = blockIdx.x >> 8;
    int h   = blockIdx.x & 255;
    int t   = threadIdx.x;     // == w
    int gin = bcast ? (g & 3) : g;
    int on  = (g >> 2) * 4 + n;

    __shared__ float sxm[32 * 256];  // X row tile [c][w]
    __shared__ float sz[1024];       // Z row      [c][kx]{re,im}
    __shared__ float sbw[1024];      // byp_w      [c][i]
    __shared__ float sbb[32];
    __shared__ float spw[32];

    {   // X tile: 4 channels per iteration, coalesced float4
        int cl = t >> 6, w4 = t & 63;
#pragma unroll
        for (int j = 0; j < 8; j++) {
            int c = j * 4 + cl;
            ((float4*)sxm)[c * 64 + w4] =
                ((const float4*)(Xin + ((size_t)(gin * CC + c)) * NPIX + h * 256))[w4];
        }
        ((float4*)sz)[t]  = ((const float4*)(g_Z + ((size_t)(g * 256 + h)) * 1024))[t];
        ((float4*)sbw)[t] = ((const float4*)(bw + (size_t)on * 1024))[t];
        if (t < 32) { sbb[t] = bb[on * 32 + t]; spw[t] = pw[t]; }
    }
    __syncthreads();

    float xcol[32];
#pragma unroll
    for (int i = 0; i < 32; i++) xcol[i] = sxm[i * 256 + t];

    float twr[16], twi[16];
    {
        float cs, ss;
        sincosf(2.0f * PI_F * (float)t * (1.0f / 256.0f), &ss, &cs);
        twr[0] = 1.0f; twi[0] = 0.0f;
#pragma unroll
        for (int k = 1; k < 16; k++) {
            float nr = twr[k - 1] * cs - twi[k - 1] * ss;
            float ni = twr[k - 1] * ss + twi[k - 1] * cs;
            twr[k] = nr; twi[k] = ni;
        }
    }

    float pacc = 0.0f;
#pragma unroll 4
    for (int c = 0; c < 32; c++) {
        const float4* zc = (const float4*)&sz[c * 32];
        const float4* bc = (const float4*)&sbw[c * 32];
        float s = 0.0f, byp = sbb[c];
#pragma unroll
        for (int q = 0; q < 8; q++) {
            float4 z = zc[q];
            s += z.x * twr[2 * q]     - z.y * twi[2 * q];
            s += z.z * twr[2 * q + 1] - z.w * twi[2 * q + 1];
            float4 bv = bc[q];
            byp += bv.x * xcol[4 * q]     + bv.y * xcol[4 * q + 1]
                 + bv.z * xcol[4 * q + 2] + bv.w * xcol[4 * q + 3];
        }
        float v  = s + byp;
        float gv = v * normcdff(v);          // exact gelu: x * Phi(x)
        if (last) pacc += spw[c] * gv;
        else      Xout[((size_t)(g * CC + c)) * NPIX + h * 256 + t] = gv;
    }
    if (last) {
        int b = g & 3, o = g >> 2;
        out[((size_t)(b * 4 + o)) * NPIX + h * 256 + t] = pacc + pb[0];
    }
}

// ======================= host launcher =======================
extern "C" void kernel_launch(void* const* d_in, const int* in_sizes, int n_in,
                              void* d_out, int out_size)
{
    const float* x  = (const float*)d_in[0];
    const float* lw = (const float*)d_in[1];
    const float* lb = (const float*)d_in[2];
    const float* wr = (const float*)d_in[3];
    const float* wi = (const float*)d_in[4];
    const float* bw = (const float*)d_in[5];
    const float* bb = (const float*)d_in[6];
    const float* pw = (const float*)d_in[7];
    const float* pb = (const float*)d_in[8];
    float* out = (float*)d_out;

    float *pA = nullptr, *pB = nullptr, *px0 = nullptr;
    cudaGetSymbolAddress((void**)&pA,  g_A);
    cudaGetSymbolAddress((void**)&pB,  g_B);
    cudaGetSymbolAddress((void**)&px0, g_x0);

    lift_kernel <<< (4 * CC * (NPIX / 4) + 255) / 256, 256 >>> (x, lw, lb);
    wprep_kernel<<< (16 * 256 * 1024) / 256, 256 >>> (wr, wi);

    const float* cur = px0;
    for (int n = 0; n < 4; n++) {
        int bcast = (n == 0);
        int last  = (n == 3);
        float* nxt = (n & 1) ? pB : pA;   // n=0->A, n=1->B, n=2->A, n=3->B(unused)

        dft_fwd_kernel <<< 512, 256 >>> (cur, bcast);
        spectral_kernel<<< 4096, 32 >>> (n);
        dft_invh_kernel<<< 512, 256 >>> ();
        finish_kernel  <<< 4096, 256 >>> (cur, nxt, bw, bb, pw, pb, out, n, bcast, last);

        cur = nxt;
    }
}

// round 5
// speedup vs baseline: 1.2415x; 1.2415x over previous
#include <cuda_runtime.h>
#include <math.h>

#define PI_F 3.14159265358979323846f

#define GG   16   // o*4 + b  (4 output chains x 4 batch)
#define CC   32   // width
#define NPIX 65536

typedef unsigned long long u64;

// ---------------- f32x2 packed helpers (Blackwell FFMA2) ----------------
__device__ __forceinline__ u64 pk2(float lo, float hi) {
    u64 r; asm("mov.b64 %0, {%1,%2};" : "=l"(r) : "f"(lo), "f"(hi)); return r;
}
__device__ __forceinline__ float2 upk(u64 v) {
    float2 f; asm("mov.b64 {%0,%1}, %2;" : "=f"(f.x), "=f"(f.y) : "l"(v)); return f;
}
__device__ __forceinline__ void fma2(u64& d, u64 a, u64 b) {
    asm("fma.rn.f32x2 %0, %1, %2, %0;" : "+l"(d) : "l"(a), "l"(b));
}

// ---- scratch (static device allocations; no cudaMalloc anywhere) ----
__device__ float g_x0[4 * CC * NPIX];            //  33.5 MB lifted input
__device__ float g_A [GG * CC * NPIX];           // 134 MB ping
__device__ float g_B [GG * CC * NPIX];           // 134 MB pong
__device__ float g_XF[GG * CC * 256 * 2];        // fwd spectrum [g][c][ky*16+kx]{re,im}
__device__ float g_Z [GG * 256 * CC * 16 * 2];   // after inv-h DFT: [g][h][c][kx]{re,im}

// ======================= lift: conv1x1 (3 -> 32) =======================
__global__ void lift_kernel(const float* __restrict__ x,
                            const float* __restrict__ lw,
                            const float* __restrict__ lb)
{
    int idx = blockIdx.x * blockDim.x + threadIdx.x;
    if (idx >= 4 * CC * (NPIX / 4)) return;
    int p4 = idx % (NPIX / 4);
    int c  = (idx / (NPIX / 4)) % CC;
    int b  = idx / ((NPIX / 4) * CC);
    const float4* xb = (const float4*)(x + (size_t)b * 3 * NPIX);
    float4 v0 = xb[p4];
    float4 v1 = xb[p4 + NPIX / 4];
    float4 v2 = xb[p4 + NPIX / 2];
    float w0 = lw[c * 3 + 0], w1 = lw[c * 3 + 1], w2 = lw[c * 3 + 2], bv = lb[c];
    float4 r;
    r.x = bv + w0 * v0.x + w1 * v1.x + w2 * v2.x;
    r.y = bv + w0 * v0.y + w1 * v1.y + w2 * v2.y;
    r.z = bv + w0 * v0.z + w1 * v1.z + w2 * v2.z;
    r.w = bv + w0 * v0.w + w1 * v1.w + w2 * v2.w;
    ((float4*)g_x0)[(size_t)(b * CC + c) * (NPIX / 4) + p4] = r;
}

// ======================= K1: forward truncated 2-D DFT =======================
// Block = one (g,c) channel image. Stage 1 (w->kx, radix 16x16, FFMA2 packed),
// stage 2 (h->ky, incremental rotation) into register accumulators.
__global__ __launch_bounds__(256, 2) void dft_fwd_kernel(const float* __restrict__ Xin, int bcast)
{
    int g   = blockIdx.x >> 5;
    int c   = blockIdx.x & 31;
    int gin = bcast ? (g & 3) : g;
    int t   = threadIdx.x;
    int kx  = t & 15;   // stage-1 kx AND stage-2 kx
    int hp  = t >> 4;   // stage-1 row id
    int ky  = t >> 4;   // stage-2 ky

    __shared__ __align__(16) float sx[32 * 256];
    __shared__ __align__(16) u64   sT[32][16];   // per-row (tr,ti)

    // stage-1 twiddle tables
    float cwb[16], swb[16], cuv[16], suv[16];
#pragma unroll
    for (int b = 0; b < 16; b++) {
        int m1 = (kx * b) & 255;
        int m2 = (kx * b) & 15;
        sincosf(-2.0f * PI_F * (float)m1 * (1.0f / 256.0f), &swb[b], &cwb[b]);
        sincosf(-2.0f * PI_F * (float)m2 * (1.0f / 16.0f),  &suv[b], &cuv[b]);
    }
    u64 cw2[8], sw2[8];
#pragma unroll
    for (int j = 0; j < 8; j++) {
        cw2[j] = pk2(cwb[2 * j], cwb[2 * j + 1]);
        sw2[j] = pk2(swb[2 * j], swb[2 * j + 1]);
    }

    // stage-2 rotation step e^{-2*pi*i*ky/256}
    float cs2, ss2;
    sincosf(-2.0f * PI_F * (float)ky * (1.0f / 256.0f), &ss2, &cs2);
    float pr = 1.0f, pq = 0.0f;
    float accR = 0.0f, accI = 0.0f;

    const float* src = Xin + ((size_t)(gin * CC + c)) * NPIX;

    for (int tile = 0; tile < 8; tile++) {
        const float4* s4 = (const float4*)(src + tile * 8192);
        float4* d4 = (float4*)sx;
#pragma unroll
        for (int j = 0; j < 8; j++) d4[t + j * 256] = s4[t + j * 256];
        __syncthreads();

        // ---- stage 1: row DFT along w (radix 16x16, packed) ----
#pragma unroll
        for (int rr = 0; rr < 2; rr++) {
            int h = hp + rr * 16;
            const ulonglong2* xr = (const ulonglong2*)&sx[h * 256];
            float tr = 0.0f, ti = 0.0f;
#pragma unroll
            for (int a = 0; a < 16; a++) {
                ulonglong2 q0 = xr[a * 4 + 0];
                ulonglong2 q1 = xr[a * 4 + 1];
                ulonglong2 q2 = xr[a * 4 + 2];
                ulonglong2 q3 = xr[a * 4 + 3];
                u64 gr = 0ULL, gi = 0ULL;
                fma2(gr, q0.x, cw2[0]); fma2(gr, q0.y, cw2[1]);
                fma2(gr, q1.x, cw2[2]); fma2(gr, q1.y, cw2[3]);
                fma2(gr, q2.x, cw2[4]); fma2(gr, q2.y, cw2[5]);
                fma2(gr, q3.x, cw2[6]); fma2(gr, q3.y, cw2[7]);
                fma2(gi, q0.x, sw2[0]); fma2(gi, q0.y, sw2[1]);
                fma2(gi, q1.x, sw2[2]); fma2(gi, q1.y, sw2[3]);
                fma2(gi, q2.x, sw2[4]); fma2(gi, q2.y, sw2[5]);
                fma2(gi, q3.x, sw2[6]); fma2(gi, q3.y, sw2[7]);
                float2 gv = upk(gr), hv = upk(gi);
                float grs = gv.x + gv.y;
                float gis = hv.x + hv.y;
                tr += grs * cuv[a] - gis * suv[a];
                ti += grs * suv[a] + gis * cuv[a];
            }
            sT[h][kx] = pk2(tr, ti);
        }
        __syncthreads();

        // ---- stage 2: accumulate over h with rotating phase ----
#pragma unroll
        for (int hl = 0; hl < 32; hl++) {
            float2 tv = upk(sT[hl][kx]);
            accR += tv.x * pr - tv.y * pq;
            accI += tv.x * pq + tv.y * pr;
            float npr = pr * cs2 - pq * ss2;
            pq = pr * ss2 + pq * cs2;
            pr = npr;
        }
        __syncthreads();
    }

    ((float2*)g_XF)[(g * CC + c) * 256 + ky * 16 + kx] = make_float2(accR, accI);
}

// ============== K2: spectral mix (fused) + inverse DFT along h ==============
// Block = (g,c), thread = kk for mixing, = h for inverse DFT.
// Weights read DIRECTLY from raw layout [on][i][c][kk] (kk contiguous -> coalesced).
// All normalization (1/65536 and c_kx) folded in after the i-sum.
__global__ __launch_bounds__(256) void mix_invh_kernel(const float* __restrict__ wr,
                                                       const float* __restrict__ wi,
                                                       int n)
{
    int g  = blockIdx.x >> 5;
    int c  = blockIdx.x & 31;
    int on = (g >> 2) * 4 + n;
    int t  = threadIdx.x;

    __shared__ __align__(16) float sYF[512];   // [ky*16+kx]{re,im}

    {   // ---- channel mix at kk = t ----
        const float2* xf  = (const float2*)g_XF + (size_t)g * CC * 256 + t;
        const float*  wrp = wr + ((size_t)on * 262144 + (size_t)c * 256) + t;
        const float*  wip = wi + ((size_t)on * 262144 + (size_t)c * 256) + t;
        float yr = 0.0f, yi = 0.0f;
#pragma unroll
        for (int i = 0; i < 32; i++) {
            float2 xv = xf[i * 256];
            float wrv = wrp[(size_t)i * 8192];
            float wiv = wip[(size_t)i * 8192];
            yr += xv.x * wrv - xv.y * wiv;
            yi += xv.x * wiv + xv.y * wrv;
        }
        float s = ((t & 15) == 0 ? 1.0f : 2.0f) * (1.0f / 65536.0f);
        sYF[2 * t]     = yr * s;
        sYF[2 * t + 1] = yi * s;
    }
    __syncthreads();

    // ---- inverse DFT along h (ky -> h = t), packed accumulators ----
    int h = t;
    u64 Zacc[16];
#pragma unroll
    for (int k = 0; k < 16; k++) Zacc[k] = 0ULL;

    float cs, ss;
    sincosf(2.0f * PI_F * (float)h * (1.0f / 256.0f), &ss, &cs);
    float pr = 1.0f, pq = 0.0f;       // e^{+2*pi*i*h*ky/256}

#pragma unroll
    for (int ky = 0; ky < 16; ky++) {
        u64 ppq  = pk2(pr, pq);
        u64 mqp  = pk2(-pq, pr);
        const float4* y4 = (const float4*)&sYF[ky * 32];
#pragma unroll
        for (int q = 0; q < 8; q++) {
            float4 y = y4[q];
            fma2(Zacc[2 * q],     pk2(y.x, y.x), ppq);
            fma2(Zacc[2 * q],     pk2(y.y, y.y), mqp);
            fma2(Zacc[2 * q + 1], pk2(y.z, y.z), ppq);
            fma2(Zacc[2 * q + 1], pk2(y.w, y.w), mqp);
        }
        float npr = pr * cs - pq * ss;
        pq = pr * ss + pq * cs;
        pr = npr;
    }

    u64* zdst = (u64*)(g_Z + ((size_t)(g * 256 + h) * CC + c) * 32);
#pragma unroll
    for (int k = 0; k < 16; k++) zdst[k] = Zacc[k];
}

// ===== K3: inverse DFT along w + bypass conv1x1 + exact gelu (+ fused proj) =====
__global__ __launch_bounds__(256, 2) void finish_kernel(const float* __restrict__ Xin,
                                                        float* __restrict__ Xout,
                                                        const float* __restrict__ bw,
                                                        const float* __restrict__ bb,
                                                        const float* __restrict__ pw,
                                                        const float* __restrict__ pb,
                                                        float* __restrict__ out,
                                                        int n, int bcast, int last)
{
    int g   = blockIdx.x >> 8;
    int h   = blockIdx.x & 255;
    int t   = threadIdx.x;     // == w
    int gin = bcast ? (g & 3) : g;
    int on  = (g >> 2) * 4 + n;

    __shared__ __align__(16) float sxm[32 * 256];  // X row tile [c][w]
    __shared__ __align__(16) float sz[1024];       // Z row      [c][kx]{re,im}
    __shared__ __align__(16) float sbw[1024];      // byp_w      [c][i]
    __shared__ float sbb[32];
    __shared__ float spw[32];

    {   // X tile: coalesced float4
        int cl = t >> 6, w4 = t & 63;
#pragma unroll
        for (int j = 0; j < 8; j++) {
            int c = j * 4 + cl;
            ((float4*)sxm)[c * 64 + w4] =
                ((const float4*)(Xin + ((size_t)(gin * CC + c)) * NPIX + h * 256))[w4];
        }
        ((float4*)sz)[t]  = ((const float4*)(g_Z + ((size_t)(g * 256 + h)) * 1024))[t];
        ((float4*)sbw)[t] = ((const float4*)(bw + (size_t)on * 1024))[t];
        if (t < 32) { sbb[t] = bb[on * 32 + t]; spw[t] = pw[t]; }
    }
    __syncthreads();

    // packed twiddles: tw2[k] = (cos(2*pi*k*t/256), -sin(2*pi*k*t/256))
    u64 tw2[16];
    {
        float cs, ss;
        sincosf(2.0f * PI_F * (float)t * (1.0f / 256.0f), &ss, &cs);
        float twr = 1.0f, twi = 0.0f;
#pragma unroll
        for (int k = 0; k < 16; k++) {
            tw2[k] = pk2(twr, -twi);
            float nr = twr * cs - twi * ss;
            twi = twr * ss + twi * cs;
            twr = nr;
        }
    }

    // packed X column pairs
    u64 xp[16];
#pragma unroll
    for (int q = 0; q < 16; q++)
        xp[q] = pk2(sxm[(2 * q) * 256 + t], sxm[(2 * q + 1) * 256 + t]);

    float pacc = 0.0f;
#pragma unroll 2
    for (int c = 0; c < 32; c++) {
        const ulonglong2* zc = (const ulonglong2*)&sz[c * 32];
        const ulonglong2* bc = (const ulonglong2*)&sbw[c * 32];
        u64 a0 = 0ULL, a1 = 0ULL;
#pragma unroll
        for (int q = 0; q < 8; q++) {
            ulonglong2 z = zc[q];
            fma2(a0, z.x, tw2[2 * q]);
            fma2(a0, z.y, tw2[2 * q + 1]);
            ulonglong2 bv = bc[q];
            fma2(a1, bv.x, xp[2 * q]);
            fma2(a1, bv.y, xp[2 * q + 1]);
        }
        float2 r0 = upk(a0), r1 = upk(a1);
        float v  = r0.x + r0.y + r1.x + r1.y + sbb[c];
        float gv = v * normcdff(v);          // exact gelu
        if (last) pacc += spw[c] * gv;
        else      Xout[((size_t)(g * CC + c)) * NPIX + h * 256 + t] = gv;
    }
    if (last) {
        int b = g & 3, o = g >> 2;
        out[((size_t)(b * 4 + o)) * NPIX + h * 256 + t] = pacc + pb[0];
    }
}

// ======================= host launcher =======================
extern "C" void kernel_launch(void* const* d_in, const int* in_sizes, int n_in,
                              void* d_out, int out_size)
{
    const float* x  = (const float*)d_in[0];
    const float* lw = (const float*)d_in[1];
    const float* lb = (const float*)d_in[2];
    const float* wr = (const float*)d_in[3];
    const float* wi = (const float*)d_in[4];
    const float* bw = (const float*)d_in[5];
    const float* bb = (const float*)d_in[6];
    const float* pw = (const float*)d_in[7];
    const float* pb = (const float*)d_in[8];
    float* out = (float*)d_out;

    float *pA = nullptr, *pB = nullptr, *px0 = nullptr;
    cudaGetSymbolAddress((void**)&pA,  g_A);
    cudaGetSymbolAddress((void**)&pB,  g_B);
    cudaGetSymbolAddress((void**)&px0, g_x0);

    lift_kernel<<< (4 * CC * (NPIX / 4) + 255) / 256, 256 >>> (x, lw, lb);

    const float* cur = px0;
    for (int n = 0; n < 4; n++) {
        int bcast = (n == 0);
        int last  = (n == 3);
        float* nxt = (n & 1) ? pB : pA;

        dft_fwd_kernel <<< 512, 256 >>> (cur, bcast);
        mix_invh_kernel<<< 512, 256 >>> (wr, wi, n);
        finish_kernel  <<< 4096, 256 >>> (cur, nxt, bw, bb, pw, pb, out, n, bcast, last);

        cur = nxt;
    }
}

// round 6
// speedup vs baseline: 1.3900x; 1.1196x over previous
#include <cuda_runtime.h>
#include <math.h>

#define PI_F 3.14159265358979323846f

#define GG   16   // o*4 + b  (4 output chains x 4 batch)
#define CC   32   // width
#define NPIX 65536

typedef unsigned long long u64;

// ---------------- f32x2 packed helpers (Blackwell FFMA2) ----------------
__device__ __forceinline__ u64 pk2(float lo, float hi) {
    u64 r; asm("mov.b64 %0, {%1,%2};" : "=l"(r) : "f"(lo), "f"(hi)); return r;
}
__device__ __forceinline__ float2 upk(u64 v) {
    float2 f; asm("mov.b64 {%0,%1}, %2;" : "=f"(f.x), "=f"(f.y) : "l"(v)); return f;
}
__device__ __forceinline__ void fma2(u64& d, u64 a, u64 b) {
    asm("fma.rn.f32x2 %0, %1, %2, %0;" : "+l"(d) : "l"(a), "l"(b));
}

// ---- scratch (static device allocations; no cudaMalloc anywhere) ----
__device__ float g_x0[4 * CC * NPIX];            //  33.5 MB lifted input
__device__ float g_A [GG * CC * NPIX];           // 134 MB ping
__device__ float g_B [GG * CC * NPIX];           // 134 MB pong
__device__ float g_XF[GG * CC * 256 * 2];        // fwd spectrum [g][c][ky*16+kx]{re,im}
__device__ float g_Z [GG * 256 * CC * 16 * 2];   // after inv-h DFT: [g][h][c][kx]{re,im}

// ======================= lift: conv1x1 (3 -> 32) =======================
__global__ void lift_kernel(const float* __restrict__ x,
                            const float* __restrict__ lw,
                            const float* __restrict__ lb)
{
    int idx = blockIdx.x * blockDim.x + threadIdx.x;
    if (idx >= 4 * CC * (NPIX / 4)) return;
    int p4 = idx % (NPIX / 4);
    int c  = (idx / (NPIX / 4)) % CC;
    int b  = idx / ((NPIX / 4) * CC);
    const float4* xb = (const float4*)(x + (size_t)b * 3 * NPIX);
    float4 v0 = xb[p4];
    float4 v1 = xb[p4 + NPIX / 4];
    float4 v2 = xb[p4 + NPIX / 2];
    float w0 = lw[c * 3 + 0], w1 = lw[c * 3 + 1], w2 = lw[c * 3 + 2], bv = lb[c];
    float4 r;
    r.x = bv + w0 * v0.x + w1 * v1.x + w2 * v2.x;
    r.y = bv + w0 * v0.y + w1 * v1.y + w2 * v2.y;
    r.z = bv + w0 * v0.z + w1 * v1.z + w2 * v2.z;
    r.w = bv + w0 * v0.w + w1 * v1.w + w2 * v2.w;
    ((float4*)g_x0)[(size_t)(b * CC + c) * (NPIX / 4) + p4] = r;
}

// ======================= K1: forward truncated 2-D DFT =======================
__global__ __launch_bounds__(256, 2) void dft_fwd_kernel(const float* __restrict__ Xin, int bcast)
{
    int g   = blockIdx.x >> 5;
    int c   = blockIdx.x & 31;
    int gin = bcast ? (g & 3) : g;
    int t   = threadIdx.x;
    int kx  = t & 15;
    int hp  = t >> 4;
    int ky  = t >> 4;

    __shared__ __align__(16) float sx[32 * 256];
    __shared__ __align__(16) u64   sT[32][16];

    float cwb[16], swb[16], cuv[16], suv[16];
#pragma unroll
    for (int b = 0; b < 16; b++) {
        int m1 = (kx * b) & 255;
        int m2 = (kx * b) & 15;
        sincosf(-2.0f * PI_F * (float)m1 * (1.0f / 256.0f), &swb[b], &cwb[b]);
        sincosf(-2.0f * PI_F * (float)m2 * (1.0f / 16.0f),  &suv[b], &cuv[b]);
    }
    u64 cw2[8], sw2[8];
#pragma unroll
    for (int j = 0; j < 8; j++) {
        cw2[j] = pk2(cwb[2 * j], cwb[2 * j + 1]);
        sw2[j] = pk2(swb[2 * j], swb[2 * j + 1]);
    }

    float cs2, ss2;
    sincosf(-2.0f * PI_F * (float)ky * (1.0f / 256.0f), &ss2, &cs2);
    float pr = 1.0f, pq = 0.0f;
    float accR = 0.0f, accI = 0.0f;

    const float* src = Xin + ((size_t)(gin * CC + c)) * NPIX;

    for (int tile = 0; tile < 8; tile++) {
        const float4* s4 = (const float4*)(src + tile * 8192);
        float4* d4 = (float4*)sx;
#pragma unroll
        for (int j = 0; j < 8; j++) d4[t + j * 256] = s4[t + j * 256];
        __syncthreads();

#pragma unroll
        for (int rr = 0; rr < 2; rr++) {
            int h = hp + rr * 16;
            const ulonglong2* xr = (const ulonglong2*)&sx[h * 256];
            float tr = 0.0f, ti = 0.0f;
#pragma unroll
            for (int a = 0; a < 16; a++) {
                ulonglong2 q0 = xr[a * 4 + 0];
                ulonglong2 q1 = xr[a * 4 + 1];
                ulonglong2 q2 = xr[a * 4 + 2];
                ulonglong2 q3 = xr[a * 4 + 3];
                u64 gr = 0ULL, gi = 0ULL;
                fma2(gr, q0.x, cw2[0]); fma2(gr, q0.y, cw2[1]);
                fma2(gr, q1.x, cw2[2]); fma2(gr, q1.y, cw2[3]);
                fma2(gr, q2.x, cw2[4]); fma2(gr, q2.y, cw2[5]);
                fma2(gr, q3.x, cw2[6]); fma2(gr, q3.y, cw2[7]);
                fma2(gi, q0.x, sw2[0]); fma2(gi, q0.y, sw2[1]);
                fma2(gi, q1.x, sw2[2]); fma2(gi, q1.y, sw2[3]);
                fma2(gi, q2.x, sw2[4]); fma2(gi, q2.y, sw2[5]);
                fma2(gi, q3.x, sw2[6]); fma2(gi, q3.y, sw2[7]);
                float2 gv = upk(gr), hv = upk(gi);
                float grs = gv.x + gv.y;
                float gis = hv.x + hv.y;
                tr += grs * cuv[a] - gis * suv[a];
                ti += grs * suv[a] + gis * cuv[a];
            }
            sT[h][kx] = pk2(tr, ti);
        }
        __syncthreads();

#pragma unroll
        for (int hl = 0; hl < 32; hl++) {
            float2 tv = upk(sT[hl][kx]);
            accR += tv.x * pr - tv.y * pq;
            accI += tv.x * pq + tv.y * pr;
            float npr = pr * cs2 - pq * ss2;
            pq = pr * ss2 + pq * cs2;
            pr = npr;
        }
        __syncthreads();
    }

    ((float2*)g_XF)[(g * CC + c) * 256 + ky * 16 + kx] = make_float2(accR, accI);
}

// ============== K2: spectral mix (fused) + inverse DFT along h ==============
__global__ __launch_bounds__(256) void mix_invh_kernel(const float* __restrict__ wr,
                                                       const float* __restrict__ wi,
                                                       int n)
{
    int g  = blockIdx.x >> 5;
    int c  = blockIdx.x & 31;
    int on = (g >> 2) * 4 + n;
    int t  = threadIdx.x;

    __shared__ __align__(16) float sYF[512];

    {   // channel mix at kk = t
        const float2* xf  = (const float2*)g_XF + (size_t)g * CC * 256 + t;
        const float*  wrp = wr + ((size_t)on * 262144 + (size_t)c * 256) + t;
        const float*  wip = wi + ((size_t)on * 262144 + (size_t)c * 256) + t;
        float yr = 0.0f, yi = 0.0f;
#pragma unroll
        for (int i = 0; i < 32; i++) {
            float2 xv = xf[i * 256];
            float wrv = wrp[(size_t)i * 8192];
            float wiv = wip[(size_t)i * 8192];
            yr += xv.x * wrv - xv.y * wiv;
            yi += xv.x * wiv + xv.y * wrv;
        }
        float s = ((t & 15) == 0 ? 1.0f : 2.0f) * (1.0f / 65536.0f);
        sYF[2 * t]     = yr * s;
        sYF[2 * t + 1] = yi * s;
    }
    __syncthreads();

    int h = t;
    u64 Zacc[16];
#pragma unroll
    for (int k = 0; k < 16; k++) Zacc[k] = 0ULL;

    float cs, ss;
    sincosf(2.0f * PI_F * (float)h * (1.0f / 256.0f), &ss, &cs);
    float pr = 1.0f, pq = 0.0f;

#pragma unroll
    for (int ky = 0; ky < 16; ky++) {
        u64 ppq  = pk2(pr, pq);
        u64 mqp  = pk2(-pq, pr);
        const float4* y4 = (const float4*)&sYF[ky * 32];
#pragma unroll
        for (int q = 0; q < 8; q++) {
            float4 y = y4[q];
            fma2(Zacc[2 * q],     pk2(y.x, y.x), ppq);
            fma2(Zacc[2 * q],     pk2(y.y, y.y), mqp);
            fma2(Zacc[2 * q + 1], pk2(y.z, y.z), ppq);
            fma2(Zacc[2 * q + 1], pk2(y.w, y.w), mqp);
        }
        float npr = pr * cs - pq * ss;
        pq = pr * ss + pq * cs;
        pr = npr;
    }

    u64* zdst = (u64*)(g_Z + ((size_t)(g * 256 + h) * CC + c) * 32);
#pragma unroll
    for (int k = 0; k < 16; k++) zdst[k] = Zacc[k];
}

// ===== K3: inverse DFT along w + bypass conv1x1 + exact gelu (+ fused proj) =====
// 2-point w-blocking: thread t computes w = t and w = t+128 using the
// half-period symmetry e^{2pi i k (w+128)/256} = (-1)^k e^{2pi i k w/256}.
// Even/odd-k spectral sums are shared between the two points -> LDS per point
// halved AND spectral FMAs per point halved.
__global__ __launch_bounds__(128, 3) void finish_kernel(const float* __restrict__ Xin,
                                                        float* __restrict__ Xout,
                                                        const float* __restrict__ bw,
                                                        const float* __restrict__ bb,
                                                        const float* __restrict__ pw,
                                                        const float* __restrict__ pb,
                                                        float* __restrict__ out,
                                                        int n, int bcast, int last)
{
    int g   = blockIdx.x >> 8;
    int h   = blockIdx.x & 255;
    int t   = threadIdx.x;     // w in [0,128); also handles w+128
    int gin = bcast ? (g & 3) : g;
    int on  = (g >> 2) * 4 + n;

    __shared__ __align__(16) float sxm[32 * 256];  // X row tile [c][w]
    __shared__ __align__(16) float sz[1024];       // Z row      [c][kx]{re,im}
    __shared__ __align__(16) float sbw[1024];      // byp_w      [c][i]
    __shared__ float sbb[32];
    __shared__ float spw[32];

    {   // X tile: 2048 float4, 128 threads -> 16 iters, coalesced
        const float4* src4 = (const float4*)(Xin + ((size_t)gin * CC) * NPIX + h * 256);
#pragma unroll
        for (int j = 0; j < 16; j++) {
            int i  = t + j * 128;
            int c  = i >> 6, w4 = i & 63;
            ((float4*)sxm)[i] = src4[(size_t)c * (NPIX / 4) + w4];
        }
        ((float4*)sz)[t]        = ((const float4*)(g_Z + ((size_t)(g * 256 + h)) * 1024))[t];
        ((float4*)sz)[t + 128]  = ((const float4*)(g_Z + ((size_t)(g * 256 + h)) * 1024))[t + 128];
        ((float4*)sbw)[t]       = ((const float4*)(bw + (size_t)on * 1024))[t];
        ((float4*)sbw)[t + 128] = ((const float4*)(bw + (size_t)on * 1024))[t + 128];
        if (t < 32) { sbb[t] = bb[on * 32 + t]; spw[t] = pw[t]; }
    }
    __syncthreads();

    // packed twiddles for w = t: tw2[k] = (cos(2pi k t/256), -sin(2pi k t/256))
    u64 tw2[16];
    {
        float cs, ss;
        sincosf(2.0f * PI_F * (float)t * (1.0f / 256.0f), &ss, &cs);
        float twr = 1.0f, twi = 0.0f;
#pragma unroll
        for (int k = 0; k < 16; k++) {
            tw2[k] = pk2(twr, -twi);
            float nr = twr * cs - twi * ss;
            twi = twr * ss + twi * cs;
            twr = nr;
        }
    }

    // packed X column pairs for both points
    u64 xp[16], xq[16];
#pragma unroll
    for (int q = 0; q < 16; q++) {
        xp[q] = pk2(sxm[(2 * q) * 256 + t],       sxm[(2 * q + 1) * 256 + t]);
        xq[q] = pk2(sxm[(2 * q) * 256 + t + 128], sxm[(2 * q + 1) * 256 + t + 128]);
    }

    float pacc1 = 0.0f, pacc2 = 0.0f;
#pragma unroll 2
    for (int c = 0; c < 32; c++) {
        const ulonglong2* zc = (const ulonglong2*)&sz[c * 32];
        const ulonglong2* bc = (const ulonglong2*)&sbw[c * 32];
        u64 aE = 0ULL, aO = 0ULL, a1 = 0ULL, a2 = 0ULL;
#pragma unroll
        for (int q = 0; q < 8; q++) {
            ulonglong2 z = zc[q];
            fma2(aE, z.x, tw2[2 * q]);       // even modes (shared by both points)
            fma2(aO, z.y, tw2[2 * q + 1]);   // odd modes
            ulonglong2 bv = bc[q];
            fma2(a1, bv.x, xp[2 * q]);
            fma2(a1, bv.y, xp[2 * q + 1]);
            fma2(a2, bv.x, xq[2 * q]);
            fma2(a2, bv.y, xq[2 * q + 1]);
        }
        float2 e = upk(aE), o = upk(aO), b1 = upk(a1), b2 = upk(a2);
        float se = e.x + e.y, so = o.x + o.y, bbv = sbb[c];
        float v1 = se + so + b1.x + b1.y + bbv;      // w = t
        float v2 = se - so + b2.x + b2.y + bbv;      // w = t+128
        float g1 = v1 * normcdff(v1);
        float g2 = v2 * normcdff(v2);
        if (last) { pacc1 += spw[c] * g1; pacc2 += spw[c] * g2; }
        else {
            float* dst = Xout + ((size_t)(g * CC + c)) * NPIX + h * 256 + t;
            dst[0]   = g1;
            dst[128] = g2;
        }
    }
    if (last) {
        int b = g & 3, o = g >> 2;
        float* dst = out + ((size_t)(b * 4 + o)) * NPIX + h * 256 + t;
        dst[0]   = pacc1 + pb[0];
        dst[128] = pacc2 + pb[0];
    }
}

// ======================= host launcher =======================
extern "C" void kernel_launch(void* const* d_in, const int* in_sizes, int n_in,
                              void* d_out, int out_size)
{
    const float* x  = (const float*)d_in[0];
    const float* lw = (const float*)d_in[1];
    const float* lb = (const float*)d_in[2];
    const float* wr = (const float*)d_in[3];
    const float* wi = (const float*)d_in[4];
    const float* bw = (const float*)d_in[5];
    const float* bb = (const float*)d_in[6];
    const float* pw = (const float*)d_in[7];
    const float* pb = (const float*)d_in[8];
    float* out = (float*)d_out;

    float *pA = nullptr, *pB = nullptr, *px0 = nullptr;
    cudaGetSymbolAddress((void**)&pA,  g_A);
    cudaGetSymbolAddress((void**)&pB,  g_B);
    cudaGetSymbolAddress((void**)&px0, g_x0);

    lift_kernel<<< (4 * CC * (NPIX / 4) + 255) / 256, 256 >>> (x, lw, lb);

    const float* cur = px0;
    for (int n = 0; n < 4; n++) {
        int bcast = (n == 0);
        int last  = (n == 3);
        float* nxt = (n & 1) ? pB : pA;

        dft_fwd_kernel <<< 512, 256 >>> (cur, bcast);
        mix_invh_kernel<<< 512, 256 >>> (wr, wi, n);
        finish_kernel  <<< 4096, 128 >>> (cur, nxt, bw, bb, pw, pb, out, n, bcast, last);

        cur = nxt;
    }
}

// round 8
// speedup vs baseline: 1.4967x; 1.0767x over previous
#include <cuda_runtime.h>
#include <math.h>

#define PI_F 3.14159265358979323846f

#define GG   16   // o*4 + b  (4 output chains x 4 batch)
#define CC   32   // width
#define NPIX 65536

typedef unsigned long long u64;

// ---------------- f32x2 packed helpers (Blackwell FFMA2) ----------------
__device__ __forceinline__ u64 pk2(float lo, float hi) {
    u64 r; asm("mov.b64 %0, {%1,%2};" : "=l"(r) : "f"(lo), "f"(hi)); return r;
}
__device__ __forceinline__ float2 upk(u64 v) {
    float2 f; asm("mov.b64 {%0,%1}, %2;" : "=f"(f.x), "=f"(f.y) : "l"(v)); return f;
}
__device__ __forceinline__ void fma2(u64& d, u64 a, u64 b) {
    asm("fma.rn.f32x2 %0, %1, %2, %0;" : "+l"(d) : "l"(a), "l"(b));
}

// ---- fast exact-grade gelu: A&S 7.1.26 erf, |err_erf| <= 1.5e-7 ----
__device__ __forceinline__ float fast_gelu(float v) {
    float x  = fabsf(v) * 0.7071067811865476f;
    float t  = __frcp_rn(fmaf(0.3275911f, x, 1.0f));
    float p  = fmaf(t, 1.061405429f, -1.453152027f);
    p = fmaf(t, p, 1.421413741f);
    p = fmaf(t, p, -0.284496736f);
    p = fmaf(t, p, 0.254829592f);
    p = p * t;
    float ex = __expf(-x * x);
    float er = fmaf(-p, ex, 1.0f);               // erf(|v|/sqrt2)
    return 0.5f * v * (1.0f + copysignf(er, v)); // v * Phi(v)
}

// ---- scratch (static device allocations; no cudaMalloc anywhere) ----
__device__ float g_x0[4 * CC * NPIX];            //  33.5 MB lifted input
__device__ float g_A [GG * CC * NPIX];           // 134 MB ping
__device__ float g_B [GG * CC * NPIX];           // 134 MB pong
__device__ float g_XF[GG * CC * 256 * 2];        // fwd spectrum [g][c][ky*16+kx]{re,im}
__device__ float g_Z [GG * 256 * CC * 16 * 2];   // after inv-h DFT: [g][h][c][kx]{re,im}

// ======================= lift: conv1x1 (3 -> 32) =======================
__global__ void lift_kernel(const float* __restrict__ x,
                            const float* __restrict__ lw,
                            const float* __restrict__ lb)
{
    int idx = blockIdx.x * blockDim.x + threadIdx.x;
    if (idx >= 4 * CC * (NPIX / 4)) return;
    int p4 = idx % (NPIX / 4);
    int c  = (idx / (NPIX / 4)) % CC;
    int b  = idx / ((NPIX / 4) * CC);
    const float4* xb = (const float4*)(x + (size_t)b * 3 * NPIX);
    float4 v0 = xb[p4];
    float4 v1 = xb[p4 + NPIX / 4];
    float4 v2 = xb[p4 + NPIX / 2];
    float w0 = lw[c * 3 + 0], w1 = lw[c * 3 + 1], w2 = lw[c * 3 + 2], bv = lb[c];
    float4 r;
    r.x = bv + w0 * v0.x + w1 * v1.x + w2 * v2.x;
    r.y = bv + w0 * v0.y + w1 * v1.y + w2 * v2.y;
    r.z = bv + w0 * v0.z + w1 * v1.z + w2 * v2.z;
    r.w = bv + w0 * v0.w + w1 * v1.w + w2 * v2.w;
    ((float4*)g_x0)[(size_t)(b * CC + c) * (NPIX / 4) + p4] = r;
}

// ======================= K1: forward truncated 2-D DFT =======================
__global__ __launch_bounds__(256, 2) void dft_fwd_kernel(const float* __restrict__ Xin, int bcast)
{
    int g   = blockIdx.x >> 5;
    int c   = blockIdx.x & 31;
    int gin = bcast ? (g & 3) : g;
    int t   = threadIdx.x;
    int kx  = t & 15;
    int hp  = t >> 4;
    int ky  = t >> 4;

    __shared__ __align__(16) float sx[32 * 256];
    __shared__ __align__(16) u64   sT[32][16];

    // packed twiddle tables (only packed forms kept live)
    u64 cw2[8], sw2[8], cu2[16], su2[16];
    {
        float cwb[16], swb[16];
#pragma unroll
        for (int b = 0; b < 16; b++) {
            int m1 = (kx * b) & 255;
            int m2 = (kx * b) & 15;
            float sb, cb, s2, c2;
            sincosf(-2.0f * PI_F * (float)m1 * (1.0f / 256.0f), &sb, &cb);
            sincosf(-2.0f * PI_F * (float)m2 * (1.0f / 16.0f),  &s2, &c2);
            cwb[b] = cb; swb[b] = sb;
            cu2[b] = pk2(c2, c2);
            su2[b] = pk2(s2, s2);
        }
#pragma unroll
        for (int j = 0; j < 8; j++) {
            cw2[j] = pk2(cwb[2 * j], cwb[2 * j + 1]);
            sw2[j] = pk2(swb[2 * j], swb[2 * j + 1]);
        }
    }

    float cs2, ss2;
    sincosf(-2.0f * PI_F * (float)ky * (1.0f / 256.0f), &ss2, &cs2);
    float pr = 1.0f, pq = 0.0f;
    float accR = 0.0f, accI = 0.0f;

    const float* src = Xin + ((size_t)(gin * CC + c)) * NPIX;

    for (int tile = 0; tile < 8; tile++) {
        const float4* s4 = (const float4*)(src + tile * 8192);
        float4* d4 = (float4*)sx;
#pragma unroll
        for (int j = 0; j < 8; j++) d4[t + j * 256] = s4[t + j * 256];
        __syncthreads();

        // ---- stage 1: row DFT along w (radix 16x16, fully packed) ----
#pragma unroll
        for (int rr = 0; rr < 2; rr++) {
            int h = hp + rr * 16;
            const ulonglong2* xr = (const ulonglong2*)&sx[h * 256];
            u64 A = 0ULL, B = 0ULL, Cc = 0ULL, D = 0ULL;
#pragma unroll
            for (int a = 0; a < 16; a++) {
                ulonglong2 q0 = xr[a * 4 + 0];
                ulonglong2 q1 = xr[a * 4 + 1];
                ulonglong2 q2 = xr[a * 4 + 2];
                ulonglong2 q3 = xr[a * 4 + 3];
                u64 gr = 0ULL, gi = 0ULL;
                fma2(gr, q0.x, cw2[0]); fma2(gr, q0.y, cw2[1]);
                fma2(gr, q1.x, cw2[2]); fma2(gr, q1.y, cw2[3]);
                fma2(gr, q2.x, cw2[4]); fma2(gr, q2.y, cw2[5]);
                fma2(gr, q3.x, cw2[6]); fma2(gr, q3.y, cw2[7]);
                fma2(gi, q0.x, sw2[0]); fma2(gi, q0.y, sw2[1]);
                fma2(gi, q1.x, sw2[2]); fma2(gi, q1.y, sw2[3]);
                fma2(gi, q2.x, sw2[4]); fma2(gi, q2.y, sw2[5]);
                fma2(gi, q3.x, sw2[6]); fma2(gi, q3.y, sw2[7]);
                // deferred combine: 4 packed accumulators, no unpack per a
                fma2(A,  gr, cu2[a]);
                fma2(B,  gi, su2[a]);
                fma2(Cc, gr, su2[a]);
                fma2(D,  gi, cu2[a]);
            }
            float2 Av = upk(A), Bv = upk(B), Cv = upk(Cc), Dv = upk(D);
            float tr = (Av.x + Av.y) - (Bv.x + Bv.y);
            float ti = (Cv.x + Cv.y) + (Dv.x + Dv.y);
            sT[h][kx] = pk2(tr, ti);
        }
        __syncthreads();

        // ---- stage 2: accumulate over h with rotating phase ----
#pragma unroll
        for (int hl = 0; hl < 32; hl++) {
            float2 tv = upk(sT[hl][kx]);
            accR += tv.x * pr - tv.y * pq;
            accI += tv.x * pq + tv.y * pr;
            float npr = pr * cs2 - pq * ss2;
            pq = pr * ss2 + pq * cs2;
            pr = npr;
        }
        __syncthreads();
    }

    ((float2*)g_XF)[(g * CC + c) * 256 + ky * 16 + kx] = make_float2(accR, accI);
}

// ============== K2: spectral mix (fused) + inverse DFT along h ==============
__global__ __launch_bounds__(256) void mix_invh_kernel(const float* __restrict__ wr,
                                                       const float* __restrict__ wi,
                                                       int n)
{
    int g  = blockIdx.x >> 5;
    int c  = blockIdx.x & 31;
    int on = (g >> 2) * 4 + n;
    int t  = threadIdx.x;

    __shared__ __align__(16) float sYF[512];

    {   // channel mix at kk = t
        const float2* xf  = (const float2*)g_XF + (size_t)g * CC * 256 + t;
        const float*  wrp = wr + ((size_t)on * 262144 + (size_t)c * 256) + t;
        const float*  wip = wi + ((size_t)on * 262144 + (size_t)c * 256) + t;
        float yr = 0.0f, yi = 0.0f;
#pragma unroll
        for (int i = 0; i < 32; i++) {
            float2 xv = xf[i * 256];
            float wrv = wrp[(size_t)i * 8192];
            float wiv = wip[(size_t)i * 8192];
            yr += xv.x * wrv - xv.y * wiv;
            yi += xv.x * wiv + xv.y * wrv;
        }
        float s = ((t & 15) == 0 ? 1.0f : 2.0f) * (1.0f / 65536.0f);
        sYF[2 * t]     = yr * s;
        sYF[2 * t + 1] = yi * s;
    }
    __syncthreads();

    int h = t;
    u64 Zacc[16];
#pragma unroll
    for (int k = 0; k < 16; k++) Zacc[k] = 0ULL;

    float cs, ss;
    sincosf(2.0f * PI_F * (float)h * (1.0f / 256.0f), &ss, &cs);
    float pr = 1.0f, pq = 0.0f;

#pragma unroll
    for (int ky = 0; ky < 16; ky++) {
        u64 ppq  = pk2(pr, pq);
        u64 mqp  = pk2(-pq, pr);
        const float4* y4 = (const float4*)&sYF[ky * 32];
#pragma unroll
        for (int q = 0; q < 8; q++) {
            float4 y = y4[q];
            fma2(Zacc[2 * q],     pk2(y.x, y.x), ppq);
            fma2(Zacc[2 * q],     pk2(y.y, y.y), mqp);
            fma2(Zacc[2 * q + 1], pk2(y.z, y.z), ppq);
            fma2(Zacc[2 * q + 1], pk2(y.w, y.w), mqp);
        }
        float npr = pr * cs - pq * ss;
        pq = pr * ss + pq * cs;
        pr = npr;
    }

    u64* zdst = (u64*)(g_Z + ((size_t)(g * 256 + h) * CC + c) * 32);
#pragma unroll
    for (int k = 0; k < 16; k++) zdst[k] = Zacc[k];
}

// ===== K3: inverse DFT along w + bypass conv1x1 + fast gelu (+ fused proj) =====
// 2-point w-blocking via half-period symmetry; even/odd spectral sums shared.
__global__ __launch_bounds__(128, 3) void finish_kernel(const float* __restrict__ Xin,
                                                        float* __restrict__ Xout,
                                                        const float* __restrict__ bw,
                                                        const float* __restrict__ bb,
                                                        const float* __restrict__ pw,
                                                        const float* __restrict__ pb,
                                                        float* __restrict__ out,
                                                        int n, int bcast, int last)
{
    int g   = blockIdx.x >> 8;
    int h   = blockIdx.x & 255;
    int t   = threadIdx.x;     // w in [0,128); also handles w+128
    int gin = bcast ? (g & 3) : g;
    int on  = (g >> 2) * 4 + n;

    __shared__ __align__(16) float sxm[32 * 256];  // X row tile [c][w]
    __shared__ __align__(16) float sz[1024];       // Z row      [c][kx]{re,im}
    __shared__ __align__(16) float sbw[1024];      // byp_w      [c][i]
    __shared__ float sbb[32];
    __shared__ float spw[32];

    {
        const float4* src4 = (const float4*)(Xin + ((size_t)gin * CC) * NPIX + h * 256);
#pragma unroll
        for (int j = 0; j < 16; j++) {
            int i  = t + j * 128;
            int c  = i >> 6, w4 = i & 63;
            ((float4*)sxm)[i] = src4[(size_t)c * (NPIX / 4) + w4];
        }
        ((float4*)sz)[t]        = ((const float4*)(g_Z + ((size_t)(g * 256 + h)) * 1024))[t];
        ((float4*)sz)[t + 128]  = ((const float4*)(g_Z + ((size_t)(g * 256 + h)) * 1024))[t + 128];
        ((float4*)sbw)[t]       = ((const float4*)(bw + (size_t)on * 1024))[t];
        ((float4*)sbw)[t + 128] = ((const float4*)(bw + (size_t)on * 1024))[t + 128];
        if (t < 32) { sbb[t] = bb[on * 32 + t]; spw[t] = pw[t]; }
    }
    __syncthreads();

    // packed twiddles for w = t: tw2[k] = (cos(2pi k t/256), -sin(2pi k t/256))
    u64 tw2[16];
    {
        float cs, ss;
        sincosf(2.0f * PI_F * (float)t * (1.0f / 256.0f), &ss, &cs);
        float twr = 1.0f, twi = 0.0f;
#pragma unroll
        for (int k = 0; k < 16; k++) {
            tw2[k] = pk2(twr, -twi);
            float nr = twr * cs - twi * ss;
            twi = twr * ss + twi * cs;
            twr = nr;
        }
    }

    // packed X column pairs for both points
    u64 xp[16], xq[16];
#pragma unroll
    for (int q = 0; q < 16; q++) {
        xp[q] = pk2(sxm[(2 * q) * 256 + t],       sxm[(2 * q + 1) * 256 + t]);
        xq[q] = pk2(sxm[(2 * q) * 256 + t + 128], sxm[(2 * q + 1) * 256 + t + 128]);
    }

    float pacc1 = 0.0f, pacc2 = 0.0f;
    float* dst0 = last ? nullptr : (Xout + ((size_t)g * CC) * NPIX + h * 256 + t);
#pragma unroll 2
    for (int c = 0; c < 32; c++) {
        const ulonglong2* zc = (const ulonglong2*)&sz[c * 32];
        const ulonglong2* bc = (const ulonglong2*)&sbw[c * 32];
        u64 aE = 0ULL, aO = 0ULL, a1 = 0ULL, a2 = 0ULL;
#pragma unroll
        for (int q = 0; q < 8; q++) {
            ulonglong2 z = zc[q];
            fma2(aE, z.x, tw2[2 * q]);       // even modes (shared by both points)
            fma2(aO, z.y, tw2[2 * q + 1]);   // odd modes
            ulonglong2 bv = bc[q];
            fma2(a1, bv.x, xp[2 * q]);
            fma2(a1, bv.y, xp[2 * q + 1]);
            fma2(a2, bv.x, xq[2 * q]);
            fma2(a2, bv.y, xq[2 * q + 1]);
        }
        float2 e = upk(aE), o = upk(aO), b1 = upk(a1), b2 = upk(a2);
        float se = e.x + e.y, so = o.x + o.y, bbv = sbb[c];
        float v1 = se + so + b1.x + b1.y + bbv;      // w = t
        float v2 = se - so + b2.x + b2.y + bbv;      // w = t+128
        float g1 = fast_gelu(v1);
        float g2 = fast_gelu(v2);
        if (last) { pacc1 += spw[c] * g1; pacc2 += spw[c] * g2; }
        else {
            dst0[0]   = g1;
            dst0[128] = g2;
            dst0 += NPIX;
        }
    }
    if (last) {
        int b = g & 3, o = g >> 2;
        float* dst = out + ((size_t)(b * 4 + o)) * NPIX + h * 256 + t;
        dst[0]   = pacc1 + pb[0];
        dst[128] = pacc2 + pb[0];
    }
}

// ======================= host launcher =======================
extern "C" void kernel_launch(void* const* d_in, const int* in_sizes, int n_in,
                              void* d_out, int out_size)
{
    const float* x  = (const float*)d_in[0];
    const float* lw = (const float*)d_in[1];
    const float* lb = (const float*)d_in[2];
    const float* wr = (const float*)d_in[3];
    const float* wi = (const float*)d_in[4];
    const float* bw = (const float*)d_in[5];
    const float* bb = (const float*)d_in[6];
    const float* pw = (const float*)d_in[7];
    const float* pb = (const float*)d_in[8];
    float* out = (float*)d_out;

    float *pA = nullptr, *pB = nullptr, *px0 = nullptr;
    cudaGetSymbolAddress((void**)&pA,  g_A);
    cudaGetSymbolAddress((void**)&pB,  g_B);
    cudaGetSymbolAddress((void**)&px0, g_x0);

    lift_kernel<<< (4 * CC * (NPIX / 4) + 255) / 256, 256 >>> (x, lw, lb);

    const float* cur = px0;
    for (int n = 0; n < 4; n++) {
        int bcast = (n == 0);
        int last  = (n == 3);
        float* nxt = (n & 1) ? pB : pA;

        dft_fwd_kernel <<< 512, 256 >>> (cur, bcast);
        mix_invh_kernel<<< 512, 256 >>> (wr, wi, n);
        finish_kernel  <<< 4096, 128 >>> (cur, nxt, bw, bb, pw, pb, out, n, bcast, last);

        cur = nxt;
    }
}

// round 12
// speedup vs baseline: 1.6601x; 1.1092x over previous
#include <cuda_runtime.h>
#include <math.h>

#define PI_F 3.14159265358979323846f

#define GG   16   // o*4 + b  (4 output chains x 4 batch)
#define CC   32   // width
#define NPIX 65536

typedef unsigned long long u64;

// ---------------- f32x2 packed helpers (Blackwell FFMA2) ----------------
__device__ __forceinline__ u64 pk2(float lo, float hi) {
    u64 r; asm("mov.b64 %0, {%1,%2};" : "=l"(r) : "f"(lo), "f"(hi)); return r;
}
__device__ __forceinline__ float2 upk(u64 v) {
    float2 f; asm("mov.b64 {%0,%1}, %2;" : "=f"(f.x), "=f"(f.y) : "l"(v)); return f;
}
__device__ __forceinline__ void fma2(u64& d, u64 a, u64 b) {
    asm("fma.rn.f32x2 %0, %1, %2, %0;" : "+l"(d) : "l"(a), "l"(b));
}

// ---- fast exact-grade gelu: A&S 7.1.26 erf, |err_erf| <= 1.5e-7 ----
__device__ __forceinline__ float fast_gelu(float v) {
    float x  = fabsf(v) * 0.7071067811865476f;
    float t  = __frcp_rn(fmaf(0.3275911f, x, 1.0f));
    float p  = fmaf(t, 1.061405429f, -1.453152027f);
    p = fmaf(t, p, 1.421413741f);
    p = fmaf(t, p, -0.284496736f);
    p = fmaf(t, p, 0.254829592f);
    p = p * t;
    float ex = __expf(-x * x);
    float er = fmaf(-p, ex, 1.0f);               // erf(|v|/sqrt2)
    return 0.5f * v * (1.0f + copysignf(er, v)); // v * Phi(v)
}

// ---- scratch (static device allocations; no cudaMalloc anywhere) ----
__device__ float g_x0[4 * CC * NPIX];            //  33.5 MB lifted input
__device__ float g_A [GG * CC * NPIX];           // 134 MB ping
__device__ float g_B [GG * CC * NPIX];           // 134 MB pong
__device__ float g_XF[GG * CC * 256 * 2];        // fwd spectrum [g][c][ky*16+kx]{re,im}
__device__ float g_Z [GG * 256 * CC * 16 * 2];   // after inv-h DFT: [g][h][c][kx]{re,im}

// ======================= lift: conv1x1 (3 -> 32) =======================
__global__ void lift_kernel(const float* __restrict__ x,
                            const float* __restrict__ lw,
                            const float* __restrict__ lb)
{
    int idx = blockIdx.x * blockDim.x + threadIdx.x;
    if (idx >= 4 * CC * (NPIX / 4)) return;
    int p4 = idx % (NPIX / 4);
    int c  = (idx / (NPIX / 4)) % CC;
    int b  = idx / ((NPIX / 4) * CC);
    const float4* xb = (const float4*)(x + (size_t)b * 3 * NPIX);
    float4 v0 = xb[p4];
    float4 v1 = xb[p4 + NPIX / 4];
    float4 v2 = xb[p4 + NPIX / 2];
    float w0 = lw[c * 3 + 0], w1 = lw[c * 3 + 1], w2 = lw[c * 3 + 2], bv = lb[c];
    float4 r;
    r.x = bv + w0 * v0.x + w1 * v1.x + w2 * v2.x;
    r.y = bv + w0 * v0.y + w1 * v1.y + w2 * v2.y;
    r.z = bv + w0 * v0.z + w1 * v1.z + w2 * v2.z;
    r.w = bv + w0 * v0.w + w1 * v1.w + w2 * v2.w;
    ((float4*)g_x0)[(size_t)(b * CC + c) * (NPIX / 4) + p4] = r;
}

// ======================= K1: forward truncated 2-D DFT =======================
// Half-period fold: F[kx] = sum_{w'<128} (x[w'] + (-1)^kx x[w'+128]) e^{-2pi i kx w'/256}
__global__ __launch_bounds__(256, 2) void dft_fwd_kernel(const float* __restrict__ Xin, int bcast)
{
    int g   = blockIdx.x >> 5;
    int c   = blockIdx.x & 31;
    int gin = bcast ? (g & 3) : g;
    int t   = threadIdx.x;
    int kx  = t & 15;
    int hp  = t >> 4;
    int ky  = t >> 4;

    __shared__ __align__(16) float sx[32 * 256];
    __shared__ __align__(16) u64   sT[32][16];

    // packed twiddle tables
    u64 cw2[8], sw2[8], cu2[8], su2[8];
    {
        float cwb[16], swb[16];
#pragma unroll
        for (int j = 0; j < 16; j++) {
            int m1 = (kx * j) & 255;
            float sb, cb;
            sincosf(-2.0f * PI_F * (float)m1 * (1.0f / 256.0f), &sb, &cb);
            cwb[j] = cb; swb[j] = sb;
        }
#pragma unroll
        for (int j = 0; j < 8; j++) {
            cw2[j] = pk2(cwb[2 * j], cwb[2 * j + 1]);
            sw2[j] = pk2(swb[2 * j], swb[2 * j + 1]);
        }
#pragma unroll
        for (int a = 0; a < 8; a++) {
            int m2 = (kx * a) & 15;
            float s2, c2;
            sincosf(-2.0f * PI_F * (float)m2 * (1.0f / 16.0f), &s2, &c2);
            cu2[a] = pk2(c2, c2);
            su2[a] = pk2(s2, s2);
        }
    }
    float sgnf = (kx & 1) ? -1.0f : 1.0f;
    u64 sgn2 = pk2(sgnf, sgnf);

    float cs2, ss2;
    sincosf(-2.0f * PI_F * (float)ky * (1.0f / 256.0f), &ss2, &cs2);
    float pr = 1.0f, pq = 0.0f;
    float accR = 0.0f, accI = 0.0f;

    const float* src = Xin + ((size_t)(gin * CC + c)) * NPIX;

    for (int tile = 0; tile < 8; tile++) {
        const float4* s4 = (const float4*)(src + tile * 8192);
        float4* d4 = (float4*)sx;
#pragma unroll
        for (int j = 0; j < 8; j++) d4[t + j * 256] = s4[t + j * 256];
        __syncthreads();

        // ---- stage 1: folded row DFT along w ----
#pragma unroll
        for (int rr = 0; rr < 2; rr++) {
            int h = hp + rr * 16;
            const ulonglong2* xr = (const ulonglong2*)&sx[h * 256];
            u64 A = 0ULL, B = 0ULL, Cc = 0ULL, D = 0ULL;
#pragma unroll
            for (int a = 0; a < 8; a++) {
                ulonglong2 qa0 = xr[a * 4 + 0];
                ulonglong2 qa1 = xr[a * 4 + 1];
                ulonglong2 qa2 = xr[a * 4 + 2];
                ulonglong2 qa3 = xr[a * 4 + 3];
                ulonglong2 qb0 = xr[a * 4 + 32];
                ulonglong2 qb1 = xr[a * 4 + 33];
                ulonglong2 qb2 = xr[a * 4 + 34];
                ulonglong2 qb3 = xr[a * 4 + 35];
                u64 f0 = qa0.x; fma2(f0, qb0.x, sgn2);
                u64 f1 = qa0.y; fma2(f1, qb0.y, sgn2);
                u64 f2 = qa1.x; fma2(f2, qb1.x, sgn2);
                u64 f3 = qa1.y; fma2(f3, qb1.y, sgn2);
                u64 f4 = qa2.x; fma2(f4, qb2.x, sgn2);
                u64 f5 = qa2.y; fma2(f5, qb2.y, sgn2);
                u64 f6 = qa3.x; fma2(f6, qb3.x, sgn2);
                u64 f7 = qa3.y; fma2(f7, qb3.y, sgn2);
                u64 gr = 0ULL, gi = 0ULL;
                fma2(gr, f0, cw2[0]); fma2(gr, f1, cw2[1]);
                fma2(gr, f2, cw2[2]); fma2(gr, f3, cw2[3]);
                fma2(gr, f4, cw2[4]); fma2(gr, f5, cw2[5]);
                fma2(gr, f6, cw2[6]); fma2(gr, f7, cw2[7]);
                fma2(gi, f0, sw2[0]); fma2(gi, f1, sw2[1]);
                fma2(gi, f2, sw2[2]); fma2(gi, f3, sw2[3]);
                fma2(gi, f4, sw2[4]); fma2(gi, f5, sw2[5]);
                fma2(gi, f6, sw2[6]); fma2(gi, f7, sw2[7]);
                fma2(A,  gr, cu2[a]);
                fma2(B,  gi, su2[a]);
                fma2(Cc, gr, su2[a]);
                fma2(D,  gi, cu2[a]);
            }
            float2 Av = upk(A), Bv = upk(B), Cv = upk(Cc), Dv = upk(D);
            float tr = (Av.x + Av.y) - (Bv.x + Bv.y);
            float ti = (Cv.x + Cv.y) + (Dv.x + Dv.y);
            sT[h][kx] = pk2(tr, ti);
        }
        __syncthreads();

        // ---- stage 2: accumulate over h with rotating phase ----
#pragma unroll
        for (int hl = 0; hl < 32; hl++) {
            float2 tv = upk(sT[hl][kx]);
            accR += tv.x * pr - tv.y * pq;
            accI += tv.x * pq + tv.y * pr;
            float npr = pr * cs2 - pq * ss2;
            pq = pr * ss2 + pq * cs2;
            pr = npr;
        }
        __syncthreads();
    }

    ((float2*)g_XF)[(g * CC + c) * 256 + ky * 16 + kx] = make_float2(accR, accI);
}

// ============== K2: spectral mix (fused) + inverse DFT along h ==============
__global__ __launch_bounds__(256) void mix_invh_kernel(const float* __restrict__ wr,
                                                       const float* __restrict__ wi,
                                                       int n)
{
    int g  = blockIdx.x >> 5;
    int c  = blockIdx.x & 31;
    int on = (g >> 2) * 4 + n;
    int t  = threadIdx.x;

    __shared__ __align__(16) float sYF[512];

    {   // channel mix at kk = t
        const float2* xf  = (const float2*)g_XF + (size_t)g * CC * 256 + t;
        const float*  wrp = wr + ((size_t)on * 262144 + (size_t)c * 256) + t;
        const float*  wip = wi + ((size_t)on * 262144 + (size_t)c * 256) + t;
        float yr = 0.0f, yi = 0.0f;
#pragma unroll
        for (int i = 0; i < 32; i++) {
            float2 xv = xf[i * 256];
            float wrv = wrp[(size_t)i * 8192];
            float wiv = wip[(size_t)i * 8192];
            yr += xv.x * wrv - xv.y * wiv;
            yi += xv.x * wiv + xv.y * wrv;
        }
        float s = ((t & 15) == 0 ? 1.0f : 2.0f) * (1.0f / 65536.0f);
        sYF[2 * t]     = yr * s;
        sYF[2 * t + 1] = yi * s;
    }
    __syncthreads();

    int h = t;
    u64 Zacc[16];
#pragma unroll
    for (int k = 0; k < 16; k++) Zacc[k] = 0ULL;

    float cs, ss;
    sincosf(2.0f * PI_F * (float)h * (1.0f / 256.0f), &ss, &cs);
    float pr = 1.0f, pq = 0.0f;

#pragma unroll
    for (int ky = 0; ky < 16; ky++) {
        u64 ppq  = pk2(pr, pq);
        u64 mqp  = pk2(-pq, pr);
        const float4* y4 = (const float4*)&sYF[ky * 32];
#pragma unroll
        for (int q = 0; q < 8; q++) {
            float4 y = y4[q];
            fma2(Zacc[2 * q],     pk2(y.x, y.x), ppq);
            fma2(Zacc[2 * q],     pk2(y.y, y.y), mqp);
            fma2(Zacc[2 * q + 1], pk2(y.z, y.z), ppq);
            fma2(Zacc[2 * q + 1], pk2(y.w, y.w), mqp);
        }
        float npr = pr * cs - pq * ss;
        pq = pr * ss + pq * cs;
        pr = npr;
    }

    u64* zdst = (u64*)(g_Z + ((size_t)(g * 256 + h) * CC + c) * 32);
#pragma unroll
    for (int k = 0; k < 16; k++) zdst[k] = Zacc[k];
}

// ===== K3: bypass GEMM pre-pass -> spectral idft-w + gelu (+ fused proj) =====
// Phase A: B[c][w] = bb[c] + sum_i bw[c][i]*x[i][w]  (8c x 8w register tile,
//          written in place over the X tile in smem).
// Phase B: per thread 2 w-points (t, t+128) via half-period symmetry; reads
//          only 8 broadcast LDS.128 (Z) + 2 scalar LDS (B) per channel.
__global__ __launch_bounds__(128, 4) void finish_kernel(const float* __restrict__ Xin,
                                                        float* __restrict__ Xout,
                                                        const float* __restrict__ bw,
                                                        const float* __restrict__ bb,
                                                        const float* __restrict__ pw,
                                                        const float* __restrict__ pb,
                                                        float* __restrict__ out,
                                                        int n, int bcast, int last)
{
    int g   = blockIdx.x >> 8;
    int h   = blockIdx.x & 255;
    int t   = threadIdx.x;     // phase B: w = t and w = t+128
    int gin = bcast ? (g & 3) : g;
    int on  = (g >> 2) * 4 + n;

    __shared__ __align__(16) float sxm[32 * 256];  // X tile [i][w] -> becomes B[c][w]
    __shared__ __align__(16) float sz[1024];       // Z row [c][kx]{re,im}
    __shared__ __align__(16) float sbwT[1024];     // bw transposed [i][c]
    __shared__ float sbb[32];
    __shared__ float spw[32];

    {   // load phase
        const float4* src4 = (const float4*)(Xin + ((size_t)gin * CC) * NPIX + h * 256);
#pragma unroll
        for (int j = 0; j < 16; j++) {
            int i  = t + j * 128;
            int c  = i >> 6, w4 = i & 63;
            ((float4*)sxm)[i] = src4[(size_t)c * (NPIX / 4) + w4];
        }
        ((float4*)sz)[t]       = ((const float4*)(g_Z + ((size_t)(g * 256 + h)) * 1024))[t];
        ((float4*)sz)[t + 128] = ((const float4*)(g_Z + ((size_t)(g * 256 + h)) * 1024))[t + 128];
        // bw transpose: [c][i] -> sbwT[i][c]  (BOTH halves: c = 0..15 and 16..31)
        {
            float4 bv4a = ((const float4*)(bw + (size_t)on * 1024))[t];
            float4 bv4b = ((const float4*)(bw + (size_t)on * 1024))[t + 128];
            int cB = t >> 3, i0 = (t & 7) * 4;
            sbwT[(i0 + 0) * 32 + cB] = bv4a.x;
            sbwT[(i0 + 1) * 32 + cB] = bv4a.y;
            sbwT[(i0 + 2) * 32 + cB] = bv4a.z;
            sbwT[(i0 + 3) * 32 + cB] = bv4a.w;
            sbwT[(i0 + 0) * 32 + cB + 16] = bv4b.x;
            sbwT[(i0 + 1) * 32 + cB + 16] = bv4b.y;
            sbwT[(i0 + 2) * 32 + cB + 16] = bv4b.z;
            sbwT[(i0 + 3) * 32 + cB + 16] = bv4b.w;
        }
        if (t < 32) { sbb[t] = bb[on * 32 + t]; spw[t] = pw[t]; }
    }
    __syncthreads();

    // ---- phase A: bypass GEMM. thread tile: c in [8*cb, 8*cb+8),
    //      w in {4*wb..4*wb+3} U {4*wb+128..4*wb+131}
    {
        int wb = t & 31, cb = t >> 5;
        int w0 = 4 * wb, c0 = 8 * cb;
        u64 acc[8][4];
#pragma unroll
        for (int cl = 0; cl < 8; cl++) {
            float bbv = sbb[c0 + cl];
            u64 bp = pk2(bbv, bbv);
            acc[cl][0] = bp; acc[cl][1] = bp; acc[cl][2] = bp; acc[cl][3] = bp;
        }
#pragma unroll 4
        for (int i = 0; i < 32; i++) {
            const ulonglong2* xr = (const ulonglong2*)&sxm[i * 256 + w0];
            ulonglong2 xa = xr[0];        // w0..w0+3
            ulonglong2 xb = xr[32];       // w0+128..w0+131
            const float4* bwr = (const float4*)&sbwT[i * 32 + c0];
            float4 b0 = bwr[0];
            float4 b1 = bwr[1];
            u64 w00 = pk2(b0.x, b0.x), w01 = pk2(b0.y, b0.y);
            u64 w02 = pk2(b0.z, b0.z), w03 = pk2(b0.w, b0.w);
            u64 w04 = pk2(b1.x, b1.x), w05 = pk2(b1.y, b1.y);
            u64 w06 = pk2(b1.z, b1.z), w07 = pk2(b1.w, b1.w);
            fma2(acc[0][0], xa.x, w00); fma2(acc[0][1], xa.y, w00);
            fma2(acc[0][2], xb.x, w00); fma2(acc[0][3], xb.y, w00);
            fma2(acc[1][0], xa.x, w01); fma2(acc[1][1], xa.y, w01);
            fma2(acc[1][2], xb.x, w01); fma2(acc[1][3], xb.y, w01);
            fma2(acc[2][0], xa.x, w02); fma2(acc[2][1], xa.y, w02);
            fma2(acc[2][2], xb.x, w02); fma2(acc[2][3], xb.y, w02);
            fma2(acc[3][0], xa.x, w03); fma2(acc[3][1], xa.y, w03);
            fma2(acc[3][2], xb.x, w03); fma2(acc[3][3], xb.y, w03);
            fma2(acc[4][0], xa.x, w04); fma2(acc[4][1], xa.y, w04);
            fma2(acc[4][2], xb.x, w04); fma2(acc[4][3], xb.y, w04);
            fma2(acc[5][0], xa.x, w05); fma2(acc[5][1], xa.y, w05);
            fma2(acc[5][2], xb.x, w05); fma2(acc[5][3], xb.y, w05);
            fma2(acc[6][0], xa.x, w06); fma2(acc[6][1], xa.y, w06);
            fma2(acc[6][2], xb.x, w06); fma2(acc[6][3], xb.y, w06);
            fma2(acc[7][0], xa.x, w07); fma2(acc[7][1], xa.y, w07);
            fma2(acc[7][2], xb.x, w07); fma2(acc[7][3], xb.y, w07);
        }
        __syncthreads();   // all X reads done before overwrite
#pragma unroll
        for (int cl = 0; cl < 8; cl++) {
            u64* dst = (u64*)&sxm[(c0 + cl) * 256 + w0];
            dst[0]  = acc[cl][0];
            dst[1]  = acc[cl][1];
            dst[64] = acc[cl][2];   // w0+128 (u64 units)
            dst[65] = acc[cl][3];
        }
    }
    __syncthreads();

    // ---- phase B: spectral inverse-w DFT + gelu ----
    // packed twiddles for w = t: tw2[k] = (cos(2pi k t/256), -sin(2pi k t/256))
    u64 tw2[16];
    {
        float cs, ss;
        sincosf(2.0f * PI_F * (float)t * (1.0f / 256.0f), &ss, &cs);
        float twr = 1.0f, twi = 0.0f;
#pragma unroll
        for (int k = 0; k < 16; k++) {
            tw2[k] = pk2(twr, -twi);
            float nr = twr * cs - twi * ss;
            twi = twr * ss + twi * cs;
            twr = nr;
        }
    }

    float pacc1 = 0.0f, pacc2 = 0.0f;
    float* dst0 = last ? nullptr : (Xout + ((size_t)g * CC) * NPIX + h * 256 + t);
#pragma unroll 2
    for (int c = 0; c < 32; c++) {
        const ulonglong2* zc = (const ulonglong2*)&sz[c * 32];
        u64 aE = 0ULL, aO = 0ULL;
#pragma unroll
        for (int q = 0; q < 8; q++) {
            ulonglong2 z = zc[q];
            fma2(aE, z.x, tw2[2 * q]);       // even modes (shared by both points)
            fma2(aO, z.y, tw2[2 * q + 1]);   // odd modes
        }
        float B1 = sxm[c * 256 + t];
        float B2 = sxm[c * 256 + t + 128];
        float2 e = upk(aE), o = upk(aO);
        float se = e.x + e.y, so = o.x + o.y;
        float v1 = se + so + B1;             // w = t
        float v2 = se - so + B2;             // w = t+128
        float g1 = fast_gelu(v1);
        float g2 = fast_gelu(v2);
        if (last) { pacc1 += spw[c] * g1; pacc2 += spw[c] * g2; }
        else {
            dst0[0]   = g1;
            dst0[128] = g2;
            dst0 += NPIX;
        }
    }
    if (last) {
        int b = g & 3, o = g >> 2;
        float* dst = out + ((size_t)(b * 4 + o)) * NPIX + h * 256 + t;
        dst[0]   = pacc1 + pb[0];
        dst[128] = pacc2 + pb[0];
    }
}

// ======================= host launcher =======================
extern "C" void kernel_launch(void* const* d_in, const int* in_sizes, int n_in,
                              void* d_out, int out_size)
{
    const float* x  = (const float*)d_in[0];
    const float* lw = (const float*)d_in[1];
    const float* lb = (const float*)d_in[2];
    const float* wr = (const float*)d_in[3];
    const float* wi = (const float*)d_in[4];
    const float* bw = (const float*)d_in[5];
    const float* bb = (const float*)d_in[6];
    const float* pw = (const float*)d_in[7];
    const float* pb = (const float*)d_in[8];
    float* out = (float*)d_out;

    float *pA = nullptr, *pB = nullptr, *px0 = nullptr;
    cudaGetSymbolAddress((void**)&pA,  g_A);
    cudaGetSymbolAddress((void**)&pB,  g_B);
    cudaGetSymbolAddress((void**)&px0, g_x0);

    lift_kernel<<< (4 * CC * (NPIX / 4) + 255) / 256, 256 >>> (x, lw, lb);

    const float* cur = px0;
    for (int n = 0; n < 4; n++) {
        int bcast = (n == 0);
        int last  = (n == 3);
        float* nxt = (n & 1) ? pB : pA;

        dft_fwd_kernel <<< 512, 256 >>> (cur, bcast);
        mix_invh_kernel<<< 512, 256 >>> (wr, wi, n);
        finish_kernel  <<< 4096, 128 >>> (cur, nxt, bw, bb, pw, pb, out, n, bcast, last);

        cur = nxt;
    }
}

// round 15
// speedup vs baseline: 1.6788x; 1.0112x over previous
#include <cuda_runtime.h>
#include <math.h>

#define PI_F 3.14159265358979323846f

#define GG   16   // o*4 + b  (4 output chains x 4 batch)
#define CC   32   // width
#define NPIX 65536

typedef unsigned long long u64;

// ---------------- f32x2 packed helpers (Blackwell FFMA2) ----------------
__device__ __forceinline__ u64 pk2(float lo, float hi) {
    u64 r; asm("mov.b64 %0, {%1,%2};" : "=l"(r) : "f"(lo), "f"(hi)); return r;
}
__device__ __forceinline__ float2 upk(u64 v) {
    float2 f; asm("mov.b64 {%0,%1}, %2;" : "=f"(f.x), "=f"(f.y) : "l"(v)); return f;
}
__device__ __forceinline__ void fma2(u64& d, u64 a, u64 b) {
    asm("fma.rn.f32x2 %0, %1, %2, %0;" : "+l"(d) : "l"(a), "l"(b));
}

// ---- fast exact-grade gelu: A&S 7.1.26 erf, |err_erf| <= 1.5e-7 ----
__device__ __forceinline__ float fast_gelu(float v) {
    float x  = fabsf(v) * 0.7071067811865476f;
    float t  = __frcp_rn(fmaf(0.3275911f, x, 1.0f));
    float p  = fmaf(t, 1.061405429f, -1.453152027f);
    p = fmaf(t, p, 1.421413741f);
    p = fmaf(t, p, -0.284496736f);
    p = fmaf(t, p, 0.254829592f);
    p = p * t;
    float ex = __expf(-x * x);
    float er = fmaf(-p, ex, 1.0f);               // erf(|v|/sqrt2)
    return 0.5f * v * (1.0f + copysignf(er, v)); // v * Phi(v)
}

// ---- scratch (static device allocations; no cudaMalloc anywhere) ----
__device__ float g_x0[4 * CC * NPIX];            //  33.5 MB lifted input
__device__ float g_A [GG * CC * NPIX];           // 134 MB ping
__device__ float g_B [GG * CC * NPIX];           // 134 MB pong
__device__ float g_XF[GG * CC * 256 * 2];        // fwd spectrum [g][c][ky*16+kx]{re,im}
__device__ float g_Z [GG * 256 * CC * 16 * 2];   // after inv-h DFT: [g][h][c][kx]{re,im}

// ======================= lift: conv1x1 (3 -> 32) =======================
__global__ void lift_kernel(const float* __restrict__ x,
                            const float* __restrict__ lw,
                            const float* __restrict__ lb)
{
    int idx = blockIdx.x * blockDim.x + threadIdx.x;
    if (idx >= 4 * CC * (NPIX / 4)) return;
    int p4 = idx % (NPIX / 4);
    int c  = (idx / (NPIX / 4)) % CC;
    int b  = idx / ((NPIX / 4) * CC);
    const float4* xb = (const float4*)(x + (size_t)b * 3 * NPIX);
    float4 v0 = xb[p4];
    float4 v1 = xb[p4 + NPIX / 4];
    float4 v2 = xb[p4 + NPIX / 2];
    float w0 = lw[c * 3 + 0], w1 = lw[c * 3 + 1], w2 = lw[c * 3 + 2], bv = lb[c];
    float4 r;
    r.x = bv + w0 * v0.x + w1 * v1.x + w2 * v2.x;
    r.y = bv + w0 * v0.y + w1 * v1.y + w2 * v2.y;
    r.z = bv + w0 * v0.z + w1 * v1.z + w2 * v2.z;
    r.w = bv + w0 * v0.w + w1 * v1.w + w2 * v2.w;
    ((float4*)g_x0)[(size_t)(b * CC + c) * (NPIX / 4) + p4] = r;
}

// ======================= K1: forward truncated 2-D DFT =======================
// Parity fold precomputed per tile: P[w'] = x[w']+x[w'+128], M[w'] = x[w']-x[w'+128].
// F[kx] = sum_{w'<128} (kx even ? P : M)[w'] e^{-2pi i kx w'/256}
__global__ __launch_bounds__(256, 2) void dft_fwd_kernel(const float* __restrict__ Xin, int bcast)
{
    int g   = blockIdx.x >> 5;
    int c   = blockIdx.x & 31;
    int gin = bcast ? (g & 3) : g;
    int t   = threadIdx.x;
    int kx  = t & 15;
    int hp  = t >> 4;
    int ky  = t >> 4;

    // P rows [32][128], 64B skew, M rows [32][128]  (skew -> even/odd kx bank-disjoint)
    __shared__ __align__(16) float sPM[2 * 4096 + 16];
    __shared__ __align__(16) u64   sT[32][16];
    float* sP = sPM;
    float* sM = sPM + 4096 + 16;

    // packed twiddle tables
    u64 cw2[8], sw2[8], cu2[8], su2[8];
    {
        float cwb[16], swb[16];
#pragma unroll
        for (int j = 0; j < 16; j++) {
            int m1 = (kx * j) & 255;
            float sb, cb;
            sincosf(-2.0f * PI_F * (float)m1 * (1.0f / 256.0f), &sb, &cb);
            cwb[j] = cb; swb[j] = sb;
        }
#pragma unroll
        for (int j = 0; j < 8; j++) {
            cw2[j] = pk2(cwb[2 * j], cwb[2 * j + 1]);
            sw2[j] = pk2(swb[2 * j], swb[2 * j + 1]);
        }
#pragma unroll
        for (int a = 0; a < 8; a++) {
            int m2 = (kx * a) & 15;
            float s2, c2;
            sincosf(-2.0f * PI_F * (float)m2 * (1.0f / 16.0f), &s2, &c2);
            cu2[a] = pk2(c2, c2);
            su2[a] = pk2(s2, s2);
        }
    }

    float cs2, ss2;
    sincosf(-2.0f * PI_F * (float)ky * (1.0f / 256.0f), &ss2, &cs2);
    float pr = 1.0f, pq = 0.0f;
    float accR = 0.0f, accI = 0.0f;

    const float* src = Xin + ((size_t)(gin * CC + c)) * NPIX;
    const float* basef = (kx & 1) ? sM : sP;
    u64 one2 = pk2(1.0f, 1.0f), neg2 = pk2(-1.0f, -1.0f);

    for (int tile = 0; tile < 8; tile++) {
        {   // load + fold
            const ulonglong2* s4 = (const ulonglong2*)(src + tile * 8192);
            ulonglong2* P4 = (ulonglong2*)sP;
            ulonglong2* M4 = (ulonglong2*)sM;
#pragma unroll
            for (int j = 0; j < 4; j++) {
                int idx = t + j * 256;          // == row*32 + w4
                int row = idx >> 5, w4 = idx & 31;
                ulonglong2 a = s4[row * 64 + w4];
                ulonglong2 b = s4[row * 64 + w4 + 32];
                ulonglong2 p, m;
                p.x = a.x; fma2(p.x, b.x, one2);
                p.y = a.y; fma2(p.y, b.y, one2);
                m.x = a.x; fma2(m.x, b.x, neg2);
                m.y = a.y; fma2(m.y, b.y, neg2);
                P4[idx] = p;
                M4[idx] = m;
            }
        }
        __syncthreads();

        // ---- stage 1: folded row DFT along w (radix 8x16) ----
#pragma unroll
        for (int rr = 0; rr < 2; rr++) {
            int h = hp + rr * 16;
            const ulonglong2* xr = (const ulonglong2*)(basef + h * 128);
            u64 A = 0ULL, B = 0ULL, Cc = 0ULL, D = 0ULL;
#pragma unroll
            for (int a = 0; a < 8; a++) {
                ulonglong2 q0 = xr[a * 4 + 0];
                ulonglong2 q1 = xr[a * 4 + 1];
                ulonglong2 q2 = xr[a * 4 + 2];
                ulonglong2 q3 = xr[a * 4 + 3];
                u64 gr = 0ULL, gi = 0ULL;
                fma2(gr, q0.x, cw2[0]); fma2(gr, q0.y, cw2[1]);
                fma2(gr, q1.x, cw2[2]); fma2(gr, q1.y, cw2[3]);
                fma2(gr, q2.x, cw2[4]); fma2(gr, q2.y, cw2[5]);
                fma2(gr, q3.x, cw2[6]); fma2(gr, q3.y, cw2[7]);
                fma2(gi, q0.x, sw2[0]); fma2(gi, q0.y, sw2[1]);
                fma2(gi, q1.x, sw2[2]); fma2(gi, q1.y, sw2[3]);
                fma2(gi, q2.x, sw2[4]); fma2(gi, q2.y, sw2[5]);
                fma2(gi, q3.x, sw2[6]); fma2(gi, q3.y, sw2[7]);
                fma2(A,  gr, cu2[a]);
                fma2(B,  gi, su2[a]);
                fma2(Cc, gr, su2[a]);
                fma2(D,  gi, cu2[a]);
            }
            float2 Av = upk(A), Bv = upk(B), Cv = upk(Cc), Dv = upk(D);
            float tr = (Av.x + Av.y) - (Bv.x + Bv.y);
            float ti = (Cv.x + Cv.y) + (Dv.x + Dv.y);
            sT[h][kx] = pk2(tr, ti);
        }
        __syncthreads();

        // ---- stage 2: accumulate over h with rotating phase ----
#pragma unroll
        for (int hl = 0; hl < 32; hl++) {
            float2 tv = upk(sT[hl][kx]);
            accR += tv.x * pr - tv.y * pq;
            accI += tv.x * pq + tv.y * pr;
            float npr = pr * cs2 - pq * ss2;
            pq = pr * ss2 + pq * cs2;
            pr = npr;
        }
        __syncthreads();
    }

    ((float2*)g_XF)[(g * CC + c) * 256 + ky * 16 + kx] = make_float2(accR, accI);
}

// ============== K2: spectral mix (fused) + inverse DFT along h ==============
__global__ __launch_bounds__(256) void mix_invh_kernel(const float* __restrict__ wr,
                                                       const float* __restrict__ wi,
                                                       int n)
{
    int g  = blockIdx.x >> 5;
    int c  = blockIdx.x & 31;
    int on = (g >> 2) * 4 + n;
    int t  = threadIdx.x;

    __shared__ __align__(16) float sYF[512];

    {   // channel mix at kk = t
        const float2* xf  = (const float2*)g_XF + (size_t)g * CC * 256 + t;
        const float*  wrp = wr + ((size_t)on * 262144 + (size_t)c * 256) + t;
        const float*  wip = wi + ((size_t)on * 262144 + (size_t)c * 256) + t;
        float yr = 0.0f, yi = 0.0f;
#pragma unroll
        for (int i = 0; i < 32; i++) {
            float2 xv = xf[i * 256];
            float wrv = wrp[(size_t)i * 8192];
            float wiv = wip[(size_t)i * 8192];
            yr += xv.x * wrv - xv.y * wiv;
            yi += xv.x * wiv + xv.y * wrv;
        }
        float s = ((t & 15) == 0 ? 1.0f : 2.0f) * (1.0f / 65536.0f);
        sYF[2 * t]     = yr * s;
        sYF[2 * t + 1] = yi * s;
    }
    __syncthreads();

    int h = t;
    u64 Zacc[16];
#pragma unroll
    for (int k = 0; k < 16; k++) Zacc[k] = 0ULL;

    float cs, ss;
    sincosf(2.0f * PI_F * (float)h * (1.0f / 256.0f), &ss, &cs);
    float pr = 1.0f, pq = 0.0f;

#pragma unroll
    for (int ky = 0; ky < 16; ky++) {
        u64 ppq  = pk2(pr, pq);
        u64 mqp  = pk2(-pq, pr);
        const float4* y4 = (const float4*)&sYF[ky * 32];
#pragma unroll
        for (int q = 0; q < 8; q++) {
            float4 y = y4[q];
            fma2(Zacc[2 * q],     pk2(y.x, y.x), ppq);
            fma2(Zacc[2 * q],     pk2(y.y, y.y), mqp);
            fma2(Zacc[2 * q + 1], pk2(y.z, y.z), ppq);
            fma2(Zacc[2 * q + 1], pk2(y.w, y.w), mqp);
        }
        float npr = pr * cs - pq * ss;
        pq = pr * ss + pq * cs;
        pr = npr;
    }

    u64* zdst = (u64*)(g_Z + ((size_t)(g * 256 + h) * CC + c) * 32);
#pragma unroll
    for (int k = 0; k < 16; k++) zdst[k] = Zacc[k];
}

// ===== K3: bypass GEMM pre-pass -> spectral idft-w + gelu (+ fused proj) =====
__global__ __launch_bounds__(128, 4) void finish_kernel(const float* __restrict__ Xin,
                                                        float* __restrict__ Xout,
                                                        const float* __restrict__ bw,
                                                        const float* __restrict__ bb,
                                                        const float* __restrict__ pw,
                                                        const float* __restrict__ pb,
                                                        float* __restrict__ out,
                                                        int n, int bcast, int last)
{
    int g   = blockIdx.x >> 8;
    int h   = blockIdx.x & 255;
    int t   = threadIdx.x;     // phase B: w = t and w = t+128
    int gin = bcast ? (g & 3) : g;
    int on  = (g >> 2) * 4 + n;

    __shared__ __align__(16) float sxm[32 * 256];  // X tile [i][w] -> becomes B[c][w]
    __shared__ __align__(16) float sz[1024];       // Z row [c][kx]{re,im}
    __shared__ __align__(16) u64   sbwT2[32 * 32]; // bw transposed+packed [i][c] = (w,w)
    __shared__ float sbb[32];
    __shared__ float spw[32];

    {   // load phase
        const float4* src4 = (const float4*)(Xin + ((size_t)gin * CC) * NPIX + h * 256);
#pragma unroll
        for (int j = 0; j < 16; j++) {
            int i  = t + j * 128;
            int c  = i >> 6, w4 = i & 63;
            ((float4*)sxm)[i] = src4[(size_t)c * (NPIX / 4) + w4];
        }
        ((float4*)sz)[t]       = ((const float4*)(g_Z + ((size_t)(g * 256 + h)) * 1024))[t];
        ((float4*)sz)[t + 128] = ((const float4*)(g_Z + ((size_t)(g * 256 + h)) * 1024))[t + 128];
        // bw transpose + lane-duplicate: [c][i] -> sbwT2[i][c] = (w,w), both c halves
        {
            float4 bv4a = ((const float4*)(bw + (size_t)on * 1024))[t];
            float4 bv4b = ((const float4*)(bw + (size_t)on * 1024))[t + 128];
            int cB = t >> 3, i0 = (t & 7) * 4;
            sbwT2[(i0 + 0) * 32 + cB] = pk2(bv4a.x, bv4a.x);
            sbwT2[(i0 + 1) * 32 + cB] = pk2(bv4a.y, bv4a.y);
            sbwT2[(i0 + 2) * 32 + cB] = pk2(bv4a.z, bv4a.z);
            sbwT2[(i0 + 3) * 32 + cB] = pk2(bv4a.w, bv4a.w);
            sbwT2[(i0 + 0) * 32 + cB + 16] = pk2(bv4b.x, bv4b.x);
            sbwT2[(i0 + 1) * 32 + cB + 16] = pk2(bv4b.y, bv4b.y);
            sbwT2[(i0 + 2) * 32 + cB + 16] = pk2(bv4b.z, bv4b.z);
            sbwT2[(i0 + 3) * 32 + cB + 16] = pk2(bv4b.w, bv4b.w);
        }
        if (t < 32) { sbb[t] = bb[on * 32 + t]; spw[t] = pw[t]; }
    }
    __syncthreads();

    // ---- phase A: bypass GEMM. thread tile: c in [8*cb, 8*cb+8),
    //      w in {4*wb..4*wb+3} U {4*wb+128..4*wb+131}
    {
        int wb = t & 31, cb = t >> 5;
        int w0 = 4 * wb, c0 = 8 * cb;
        u64 acc[8][4];
#pragma unroll
        for (int cl = 0; cl < 8; cl++) {
            float bbv = sbb[c0 + cl];
            u64 bp = pk2(bbv, bbv);
            acc[cl][0] = bp; acc[cl][1] = bp; acc[cl][2] = bp; acc[cl][3] = bp;
        }
#pragma unroll 4
        for (int i = 0; i < 32; i++) {
            const ulonglong2* xr = (const ulonglong2*)&sxm[i * 256 + w0];
            ulonglong2 xa = xr[0];        // w0..w0+3
            ulonglong2 xb = xr[32];       // w0+128..w0+131
            const ulonglong2* bwr = (const ulonglong2*)&sbwT2[i * 32 + c0];
            ulonglong2 b01 = bwr[0];      // broadcast, pre-packed (w,w)
            ulonglong2 b23 = bwr[1];
            ulonglong2 b45 = bwr[2];
            ulonglong2 b67 = bwr[3];
            fma2(acc[0][0], xa.x, b01.x); fma2(acc[0][1], xa.y, b01.x);
            fma2(acc[0][2], xb.x, b01.x); fma2(acc[0][3], xb.y, b01.x);
            fma2(acc[1][0], xa.x, b01.y); fma2(acc[1][1], xa.y, b01.y);
            fma2(acc[1][2], xb.x, b01.y); fma2(acc[1][3], xb.y, b01.y);
            fma2(acc[2][0], xa.x, b23.x); fma2(acc[2][1], xa.y, b23.x);
            fma2(acc[2][2], xb.x, b23.x); fma2(acc[2][3], xb.y, b23.x);
            fma2(acc[3][0], xa.x, b23.y); fma2(acc[3][1], xa.y, b23.y);
            fma2(acc[3][2], xb.x, b23.y); fma2(acc[3][3], xb.y, b23.y);
            fma2(acc[4][0], xa.x, b45.x); fma2(acc[4][1], xa.y, b45.x);
            fma2(acc[4][2], xb.x, b45.x); fma2(acc[4][3], xb.y, b45.x);
            fma2(acc[5][0], xa.x, b45.y); fma2(acc[5][1], xa.y, b45.y);
            fma2(acc[5][2], xb.x, b45.y); fma2(acc[5][3], xb.y, b45.y);
            fma2(acc[6][0], xa.x, b67.x); fma2(acc[6][1], xa.y, b67.x);
            fma2(acc[6][2], xb.x, b67.x); fma2(acc[6][3], xb.y, b67.x);
            fma2(acc[7][0], xa.x, b67.y); fma2(acc[7][1], xa.y, b67.y);
            fma2(acc[7][2], xb.x, b67.y); fma2(acc[7][3], xb.y, b67.y);
        }
        __syncthreads();   // all X reads done before overwrite
#pragma unroll
        for (int cl = 0; cl < 8; cl++) {
            u64* dst = (u64*)&sxm[(c0 + cl) * 256 + w0];
            dst[0]  = acc[cl][0];
            dst[1]  = acc[cl][1];
            dst[64] = acc[cl][2];   // w0+128 (u64 units)
            dst[65] = acc[cl][3];
        }
    }
    __syncthreads();

    // ---- phase B: spectral inverse-w DFT + gelu ----
    u64 tw2[16];
    {
        float cs, ss;
        sincosf(2.0f * PI_F * (float)t * (1.0f / 256.0f), &ss, &cs);
        float twr = 1.0f, twi = 0.0f;
#pragma unroll
        for (int k = 0; k < 16; k++) {
            tw2[k] = pk2(twr, -twi);
            float nr = twr * cs - twi * ss;
            twi = twr * ss + twi * cs;
            twr = nr;
        }
    }

    float pacc1 = 0.0f, pacc2 = 0.0f;
    float* dst0 = last ? nullptr : (Xout + ((size_t)g * CC) * NPIX + h * 256 + t);
#pragma unroll 2
    for (int c = 0; c < 32; c++) {
        const ulonglong2* zc = (const ulonglong2*)&sz[c * 32];
        u64 aE = 0ULL, aO = 0ULL;
#pragma unroll
        for (int q = 0; q < 8; q++) {
            ulonglong2 z = zc[q];
            fma2(aE, z.x, tw2[2 * q]);       // even modes (shared by both points)
            fma2(aO, z.y, tw2[2 * q + 1]);   // odd modes
        }
        float B1 = sxm[c * 256 + t];
        float B2 = sxm[c * 256 + t + 128];
        float2 e = upk(aE), o = upk(aO);
        float se = e.x + e.y, so = o.x + o.y;
        float v1 = se + so + B1;             // w = t
        float v2 = se - so + B2;             // w = t+128
        float g1 = fast_gelu(v1);
        float g2 = fast_gelu(v2);
        if (last) { pacc1 += spw[c] * g1; pacc2 += spw[c] * g2; }
        else {
            dst0[0]   = g1;
            dst0[128] = g2;
            dst0 += NPIX;
        }
    }
    if (last) {
        int b = g & 3, o = g >> 2;
        float* dst = out + ((size_t)(b * 4 + o)) * NPIX + h * 256 + t;
        dst[0]   = pacc1 + pb[0];
        dst[128] = pacc2 + pb[0];
    }
}

// ======================= host launcher =======================
extern "C" void kernel_launch(void* const* d_in, const int* in_sizes, int n_in,
                              void* d_out, int out_size)
{
    const float* x  = (const float*)d_in[0];
    const float* lw = (const float*)d_in[1];
    const float* lb = (const float*)d_in[2];
    const float* wr = (const float*)d_in[3];
    const float* wi = (const float*)d_in[4];
    const float* bw = (const float*)d_in[5];
    const float* bb = (const float*)d_in[6];
    const float* pw = (const float*)d_in[7];
    const float* pb = (const float*)d_in[8];
    float* out = (float*)d_out;

    float *pA = nullptr, *pB = nullptr, *px0 = nullptr;
    cudaGetSymbolAddress((void**)&pA,  g_A);
    cudaGetSymbolAddress((void**)&pB,  g_B);
    cudaGetSymbolAddress((void**)&px0, g_x0);

    lift_kernel<<< (4 * CC * (NPIX / 4) + 255) / 256, 256 >>> (x, lw, lb);

    const float* cur = px0;
    for (int n = 0; n < 4; n++) {
        int bcast = (n == 0);
        int last  = (n == 3);
        float* nxt = (n & 1) ? pB : pA;

        dft_fwd_kernel <<< 512, 256 >>> (cur, bcast);
        mix_invh_kernel<<< 512, 256 >>> (wr, wi, n);
        finish_kernel  <<< 4096, 128 >>> (cur, nxt, bw, bb, pw, pb, out, n, bcast, last);

        cur = nxt;
    }
}

// round 16
// speedup vs baseline: 1.7644x; 1.0510x over previous
#include <cuda_runtime.h>
#include <math.h>

#define PI_F 3.14159265358979323846f

#define GG   16   // o*4 + b  (4 output chains x 4 batch)
#define CC   32   // width
#define NPIX 65536

typedef unsigned long long u64;

// ---------------- f32x2 packed helpers (Blackwell FFMA2) ----------------
__device__ __forceinline__ u64 pk2(float lo, float hi) {
    u64 r; asm("mov.b64 %0, {%1,%2};" : "=l"(r) : "f"(lo), "f"(hi)); return r;
}
__device__ __forceinline__ float2 upk(u64 v) {
    float2 f; asm("mov.b64 {%0,%1}, %2;" : "=f"(f.x), "=f"(f.y) : "l"(v)); return f;
}
__device__ __forceinline__ void fma2(u64& d, u64 a, u64 b) {
    asm("fma.rn.f32x2 %0, %1, %2, %0;" : "+l"(d) : "l"(a), "l"(b));
}

// ---- fast exact-grade gelu: A&S 7.1.26 erf, |err_erf| <= 1.5e-7 ----
__device__ __forceinline__ float fast_gelu(float v) {
    float x  = fabsf(v) * 0.7071067811865476f;
    float t  = __frcp_rn(fmaf(0.3275911f, x, 1.0f));
    float p  = fmaf(t, 1.061405429f, -1.453152027f);
    p = fmaf(t, p, 1.421413741f);
    p = fmaf(t, p, -0.284496736f);
    p = fmaf(t, p, 0.254829592f);
    p = p * t;
    float ex = __expf(-x * x);
    float er = fmaf(-p, ex, 1.0f);               // erf(|v|/sqrt2)
    return 0.5f * v * (1.0f + copysignf(er, v)); // v * Phi(v)
}

// ---- scratch (static device allocations; no cudaMalloc anywhere) ----
__device__ float g_x0[4 * CC * NPIX];            //  33.5 MB lifted input
__device__ float g_A [GG * CC * NPIX];           // 134 MB ping
__device__ float g_B [GG * CC * NPIX];           // 134 MB pong
__device__ float g_XF[GG * CC * 256 * 2];        // fwd spectrum [g][c][ky*16+kx]{re,im}
__device__ float g_Z [GG * 256 * CC * 16 * 2];   // after inv-h DFT: [g][h][c][kx]{re,im}

// ======================= lift: conv1x1 (3 -> 32) =======================
__global__ void lift_kernel(const float* __restrict__ x,
                            const float* __restrict__ lw,
                            const float* __restrict__ lb)
{
    int idx = blockIdx.x * blockDim.x + threadIdx.x;
    if (idx >= 4 * CC * (NPIX / 4)) return;
    int p4 = idx % (NPIX / 4);
    int c  = (idx / (NPIX / 4)) % CC;
    int b  = idx / ((NPIX / 4) * CC);
    const float4* xb = (const float4*)(x + (size_t)b * 3 * NPIX);
    float4 v0 = xb[p4];
    float4 v1 = xb[p4 + NPIX / 4];
    float4 v2 = xb[p4 + NPIX / 2];
    float w0 = lw[c * 3 + 0], w1 = lw[c * 3 + 1], w2 = lw[c * 3 + 2], bv = lb[c];
    float4 r;
    r.x = bv + w0 * v0.x + w1 * v1.x + w2 * v2.x;
    r.y = bv + w0 * v0.y + w1 * v1.y + w2 * v2.y;
    r.z = bv + w0 * v0.z + w1 * v1.z + w2 * v2.z;
    r.w = bv + w0 * v0.w + w1 * v1.w + w2 * v2.w;
    ((float4*)g_x0)[(size_t)(b * CC + c) * (NPIX / 4) + p4] = r;
}

// ======================= K1: forward truncated 2-D DFT =======================
// Parity fold precomputed per tile: P[w'] = x[w']+x[w'+128], M[w'] = x[w']-x[w'+128].
// F[kx] = sum_{w'<128} (kx even ? P : M)[w'] e^{-2pi i kx w'/256}
__global__ __launch_bounds__(256, 2) void dft_fwd_kernel(const float* __restrict__ Xin, int bcast)
{
    int g   = blockIdx.x >> 5;
    int c   = blockIdx.x & 31;
    int gin = bcast ? (g & 3) : g;
    int t   = threadIdx.x;
    int kx  = t & 15;
    int hp  = t >> 4;
    int ky  = t >> 4;

    // P rows [32][128], 64B skew, M rows [32][128]
    __shared__ __align__(16) float sPM[2 * 4096 + 16];
    __shared__ __align__(16) u64   sT[32][16];
    float* sP = sPM;
    float* sM = sPM + 4096 + 16;

    // packed twiddle tables
    u64 cw2[8], sw2[8], cu2[8], su2[8];
    {
        float cwb[16], swb[16];
#pragma unroll
        for (int j = 0; j < 16; j++) {
            int m1 = (kx * j) & 255;
            float sb, cb;
            sincosf(-2.0f * PI_F * (float)m1 * (1.0f / 256.0f), &sb, &cb);
            cwb[j] = cb; swb[j] = sb;
        }
#pragma unroll
        for (int j = 0; j < 8; j++) {
            cw2[j] = pk2(cwb[2 * j], cwb[2 * j + 1]);
            sw2[j] = pk2(swb[2 * j], swb[2 * j + 1]);
        }
#pragma unroll
        for (int a = 0; a < 8; a++) {
            int m2 = (kx * a) & 15;
            float s2, c2;
            sincosf(-2.0f * PI_F * (float)m2 * (1.0f / 16.0f), &s2, &c2);
            cu2[a] = pk2(c2, c2);
            su2[a] = pk2(s2, s2);
        }
    }

    float cs2, ss2;
    sincosf(-2.0f * PI_F * (float)ky * (1.0f / 256.0f), &ss2, &cs2);
    float pr = 1.0f, pq = 0.0f;
    float accR = 0.0f, accI = 0.0f;

    const float* src = Xin + ((size_t)(gin * CC + c)) * NPIX;
    const float* basef = (kx & 1) ? sM : sP;
    u64 one2 = pk2(1.0f, 1.0f), neg2 = pk2(-1.0f, -1.0f);

    for (int tile = 0; tile < 8; tile++) {
        {   // load + fold
            const ulonglong2* s4 = (const ulonglong2*)(src + tile * 8192);
            ulonglong2* P4 = (ulonglong2*)sP;
            ulonglong2* M4 = (ulonglong2*)sM;
#pragma unroll
            for (int j = 0; j < 4; j++) {
                int idx = t + j * 256;          // == row*32 + w4
                int row = idx >> 5, w4 = idx & 31;
                ulonglong2 a = s4[row * 64 + w4];
                ulonglong2 b = s4[row * 64 + w4 + 32];
                ulonglong2 p, m;
                p.x = a.x; fma2(p.x, b.x, one2);
                p.y = a.y; fma2(p.y, b.y, one2);
                m.x = a.x; fma2(m.x, b.x, neg2);
                m.y = a.y; fma2(m.y, b.y, neg2);
                P4[idx] = p;
                M4[idx] = m;
            }
        }
        __syncthreads();

        // ---- stage 1: folded row DFT along w (radix 8x16) ----
#pragma unroll
        for (int rr = 0; rr < 2; rr++) {
            int h = hp + rr * 16;
            const ulonglong2* xr = (const ulonglong2*)(basef + h * 128);
            u64 A = 0ULL, B = 0ULL, Cc = 0ULL, D = 0ULL;
#pragma unroll
            for (int a = 0; a < 8; a++) {
                ulonglong2 q0 = xr[a * 4 + 0];
                ulonglong2 q1 = xr[a * 4 + 1];
                ulonglong2 q2 = xr[a * 4 + 2];
                ulonglong2 q3 = xr[a * 4 + 3];
                u64 gr = 0ULL, gi = 0ULL;
                fma2(gr, q0.x, cw2[0]); fma2(gr, q0.y, cw2[1]);
                fma2(gr, q1.x, cw2[2]); fma2(gr, q1.y, cw2[3]);
                fma2(gr, q2.x, cw2[4]); fma2(gr, q2.y, cw2[5]);
                fma2(gr, q3.x, cw2[6]); fma2(gr, q3.y, cw2[7]);
                fma2(gi, q0.x, sw2[0]); fma2(gi, q0.y, sw2[1]);
                fma2(gi, q1.x, sw2[2]); fma2(gi, q1.y, sw2[3]);
                fma2(gi, q2.x, sw2[4]); fma2(gi, q2.y, sw2[5]);
                fma2(gi, q3.x, sw2[6]); fma2(gi, q3.y, sw2[7]);
                fma2(A,  gr, cu2[a]);
                fma2(B,  gi, su2[a]);
                fma2(Cc, gr, su2[a]);
                fma2(D,  gi, cu2[a]);
            }
            float2 Av = upk(A), Bv = upk(B), Cv = upk(Cc), Dv = upk(D);
            float tr = (Av.x + Av.y) - (Bv.x + Bv.y);
            float ti = (Cv.x + Cv.y) + (Dv.x + Dv.y);
            sT[h][kx] = pk2(tr, ti);
        }
        __syncthreads();

        // ---- stage 2: accumulate over h with rotating phase ----
#pragma unroll
        for (int hl = 0; hl < 32; hl++) {
            float2 tv = upk(sT[hl][kx]);
            accR += tv.x * pr - tv.y * pq;
            accI += tv.x * pq + tv.y * pr;
            float npr = pr * cs2 - pq * ss2;
            pq = pr * ss2 + pq * cs2;
            pr = npr;
        }
        __syncthreads();
    }

    ((float2*)g_XF)[(g * CC + c) * 256 + ky * 16 + kx] = make_float2(accR, accI);
}

// ============== K2: spectral mix (fused) + inverse DFT along h ==============
__global__ __launch_bounds__(256) void mix_invh_kernel(const float* __restrict__ wr,
                                                       const float* __restrict__ wi,
                                                       int n)
{
    int g  = blockIdx.x >> 5;
    int c  = blockIdx.x & 31;
    int on = (g >> 2) * 4 + n;
    int t  = threadIdx.x;

    __shared__ __align__(16) float sYF[512];

    {   // channel mix at kk = t
        const float2* xf  = (const float2*)g_XF + (size_t)g * CC * 256 + t;
        const float*  wrp = wr + ((size_t)on * 262144 + (size_t)c * 256) + t;
        const float*  wip = wi + ((size_t)on * 262144 + (size_t)c * 256) + t;
        float yr = 0.0f, yi = 0.0f;
#pragma unroll
        for (int i = 0; i < 32; i++) {
            float2 xv = xf[i * 256];
            float wrv = wrp[(size_t)i * 8192];
            float wiv = wip[(size_t)i * 8192];
            yr += xv.x * wrv - xv.y * wiv;
            yi += xv.x * wiv + xv.y * wrv;
        }
        float s = ((t & 15) == 0 ? 1.0f : 2.0f) * (1.0f / 65536.0f);
        sYF[2 * t]     = yr * s;
        sYF[2 * t + 1] = yi * s;
    }
    __syncthreads();

    int h = t;
    u64 Zacc[16];
#pragma unroll
    for (int k = 0; k < 16; k++) Zacc[k] = 0ULL;

    float cs, ss;
    sincosf(2.0f * PI_F * (float)h * (1.0f / 256.0f), &ss, &cs);
    float pr = 1.0f, pq = 0.0f;

#pragma unroll
    for (int ky = 0; ky < 16; ky++) {
        u64 ppq  = pk2(pr, pq);
        u64 mqp  = pk2(-pq, pr);
        const float4* y4 = (const float4*)&sYF[ky * 32];
#pragma unroll
        for (int q = 0; q < 8; q++) {
            float4 y = y4[q];
            fma2(Zacc[2 * q],     pk2(y.x, y.x), ppq);
            fma2(Zacc[2 * q],     pk2(y.y, y.y), mqp);
            fma2(Zacc[2 * q + 1], pk2(y.z, y.z), ppq);
            fma2(Zacc[2 * q + 1], pk2(y.w, y.w), mqp);
        }
        float npr = pr * cs - pq * ss;
        pq = pr * ss + pq * cs;
        pr = npr;
    }

    u64* zdst = (u64*)(g_Z + ((size_t)(g * 256 + h) * CC + c) * 32);
#pragma unroll
    for (int k = 0; k < 16; k++) zdst[k] = Zacc[k];
}

// ===== K3: bypass GEMM pre-pass -> spectral idft-w + gelu (+ fused proj) =====
// (R11 form: scalar sbwT floats + in-loop pk2 — measured fastest variant)
__global__ __launch_bounds__(128, 4) void finish_kernel(const float* __restrict__ Xin,
                                                        float* __restrict__ Xout,
                                                        const float* __restrict__ bw,
                                                        const float* __restrict__ bb,
                                                        const float* __restrict__ pw,
                                                        const float* __restrict__ pb,
                                                        float* __restrict__ out,
                                                        int n, int bcast, int last)
{
    int g   = blockIdx.x >> 8;
    int h   = blockIdx.x & 255;
    int t   = threadIdx.x;     // phase B: w = t and w = t+128
    int gin = bcast ? (g & 3) : g;
    int on  = (g >> 2) * 4 + n;

    __shared__ __align__(16) float sxm[32 * 256];  // X tile [i][w] -> becomes B[c][w]
    __shared__ __align__(16) float sz[1024];       // Z row [c][kx]{re,im}
    __shared__ __align__(16) float sbwT[1024];     // bw transposed [i][c]
    __shared__ float sbb[32];
    __shared__ float spw[32];

    {   // load phase
        const float4* src4 = (const float4*)(Xin + ((size_t)gin * CC) * NPIX + h * 256);
#pragma unroll
        for (int j = 0; j < 16; j++) {
            int i  = t + j * 128;
            int c  = i >> 6, w4 = i & 63;
            ((float4*)sxm)[i] = src4[(size_t)c * (NPIX / 4) + w4];
        }
        ((float4*)sz)[t]       = ((const float4*)(g_Z + ((size_t)(g * 256 + h)) * 1024))[t];
        ((float4*)sz)[t + 128] = ((const float4*)(g_Z + ((size_t)(g * 256 + h)) * 1024))[t + 128];
        // bw transpose: [c][i] -> sbwT[i][c]  (BOTH halves: c = 0..15 and 16..31)
        {
            float4 bv4a = ((const float4*)(bw + (size_t)on * 1024))[t];
            float4 bv4b = ((const float4*)(bw + (size_t)on * 1024))[t + 128];
            int cB = t >> 3, i0 = (t & 7) * 4;
            sbwT[(i0 + 0) * 32 + cB] = bv4a.x;
            sbwT[(i0 + 1) * 32 + cB] = bv4a.y;
            sbwT[(i0 + 2) * 32 + cB] = bv4a.z;
            sbwT[(i0 + 3) * 32 + cB] = bv4a.w;
            sbwT[(i0 + 0) * 32 + cB + 16] = bv4b.x;
            sbwT[(i0 + 1) * 32 + cB + 16] = bv4b.y;
            sbwT[(i0 + 2) * 32 + cB + 16] = bv4b.z;
            sbwT[(i0 + 3) * 32 + cB + 16] = bv4b.w;
        }
        if (t < 32) { sbb[t] = bb[on * 32 + t]; spw[t] = pw[t]; }
    }
    __syncthreads();

    // ---- phase A: bypass GEMM. thread tile: c in [8*cb, 8*cb+8),
    //      w in {4*wb..4*wb+3} U {4*wb+128..4*wb+131}
    {
        int wb = t & 31, cb = t >> 5;
        int w0 = 4 * wb, c0 = 8 * cb;
        u64 acc[8][4];
#pragma unroll
        for (int cl = 0; cl < 8; cl++) {
            float bbv = sbb[c0 + cl];
            u64 bp = pk2(bbv, bbv);
            acc[cl][0] = bp; acc[cl][1] = bp; acc[cl][2] = bp; acc[cl][3] = bp;
        }
#pragma unroll 4
        for (int i = 0; i < 32; i++) {
            const ulonglong2* xr = (const ulonglong2*)&sxm[i * 256 + w0];
            ulonglong2 xa = xr[0];        // w0..w0+3
            ulonglong2 xb = xr[32];       // w0+128..w0+131
            const float4* bwr = (const float4*)&sbwT[i * 32 + c0];
            float4 b0 = bwr[0];
            float4 b1 = bwr[1];
            u64 w00 = pk2(b0.x, b0.x), w01 = pk2(b0.y, b0.y);
            u64 w02 = pk2(b0.z, b0.z), w03 = pk2(b0.w, b0.w);
            u64 w04 = pk2(b1.x, b1.x), w05 = pk2(b1.y, b1.y);
            u64 w06 = pk2(b1.z, b1.z), w07 = pk2(b1.w, b1.w);
            fma2(acc[0][0], xa.x, w00); fma2(acc[0][1], xa.y, w00);
            fma2(acc[0][2], xb.x, w00); fma2(acc[0][3], xb.y, w00);
            fma2(acc[1][0], xa.x, w01); fma2(acc[1][1], xa.y, w01);
            fma2(acc[1][2], xb.x, w01); fma2(acc[1][3], xb.y, w01);
            fma2(acc[2][0], xa.x, w02); fma2(acc[2][1], xa.y, w02);
            fma2(acc[2][2], xb.x, w02); fma2(acc[2][3], xb.y, w02);
            fma2(acc[3][0], xa.x, w03); fma2(acc[3][1], xa.y, w03);
            fma2(acc[3][2], xb.x, w03); fma2(acc[3][3], xb.y, w03);
            fma2(acc[4][0], xa.x, w04); fma2(acc[4][1], xa.y, w04);
            fma2(acc[4][2], xb.x, w04); fma2(acc[4][3], xb.y, w04);
            fma2(acc[5][0], xa.x, w05); fma2(acc[5][1], xa.y, w05);
            fma2(acc[5][2], xb.x, w05); fma2(acc[5][3], xb.y, w05);
            fma2(acc[6][0], xa.x, w06); fma2(acc[6][1], xa.y, w06);
            fma2(acc[6][2], xb.x, w06); fma2(acc[6][3], xb.y, w06);
            fma2(acc[7][0], xa.x, w07); fma2(acc[7][1], xa.y, w07);
            fma2(acc[7][2], xb.x, w07); fma2(acc[7][3], xb.y, w07);
        }
        __syncthreads();   // all X reads done before overwrite
#pragma unroll
        for (int cl = 0; cl < 8; cl++) {
            u64* dst = (u64*)&sxm[(c0 + cl) * 256 + w0];
            dst[0]  = acc[cl][0];
            dst[1]  = acc[cl][1];
            dst[64] = acc[cl][2];   // w0+128 (u64 units)
            dst[65] = acc[cl][3];
        }
    }
    __syncthreads();

    // ---- phase B: spectral inverse-w DFT + gelu ----
    u64 tw2[16];
    {
        float cs, ss;
        sincosf(2.0f * PI_F * (float)t * (1.0f / 256.0f), &ss, &cs);
        float twr = 1.0f, twi = 0.0f;
#pragma unroll
        for (int k = 0; k < 16; k++) {
            tw2[k] = pk2(twr, -twi);
            float nr = twr * cs - twi * ss;
            twi = twr * ss + twi * cs;
            twr = nr;
        }
    }

    float pacc1 = 0.0f, pacc2 = 0.0f;
    float* dst0 = last ? nullptr : (Xout + ((size_t)g * CC) * NPIX + h * 256 + t);
#pragma unroll 2
    for (int c = 0; c < 32; c++) {
        const ulonglong2* zc = (const ulonglong2*)&sz[c * 32];
        u64 aE = 0ULL, aO = 0ULL;
#pragma unroll
        for (int q = 0; q < 8; q++) {
            ulonglong2 z = zc[q];
            fma2(aE, z.x, tw2[2 * q]);       // even modes (shared by both points)
            fma2(aO, z.y, tw2[2 * q + 1]);   // odd modes
        }
        float B1 = sxm[c * 256 + t];
        float B2 = sxm[c * 256 + t + 128];
        float2 e = upk(aE), o = upk(aO);
        float se = e.x + e.y, so = o.x + o.y;
        float v1 = se + so + B1;             // w = t
        float v2 = se - so + B2;             // w = t+128
        float g1 = fast_gelu(v1);
        float g2 = fast_gelu(v2);
        if (last) { pacc1 += spw[c] * g1; pacc2 += spw[c] * g2; }
        else {
            dst0[0]   = g1;
            dst0[128] = g2;
            dst0 += NPIX;
        }
    }
    if (last) {
        int b = g & 3, o = g >> 2;
        float* dst = out + ((size_t)(b * 4 + o)) * NPIX + h * 256 + t;
        dst[0]   = pacc1 + pb[0];
        dst[128] = pacc2 + pb[0];
    }
}

// ======================= host launcher =======================
extern "C" void kernel_launch(void* const* d_in, const int* in_sizes, int n_in,
                              void* d_out, int out_size)
{
    const float* x  = (const float*)d_in[0];
    const float* lw = (const float*)d_in[1];
    const float* lb = (const float*)d_in[2];
    const float* wr = (const float*)d_in[3];
    const float* wi = (const float*)d_in[4];
    const float* bw = (const float*)d_in[5];
    const float* bb = (const float*)d_in[6];
    const float* pw = (const float*)d_in[7];
    const float* pb = (const float*)d_in[8];
    float* out = (float*)d_out;

    float *pA = nullptr, *pB = nullptr, *px0 = nullptr;
    cudaGetSymbolAddress((void**)&pA,  g_A);
    cudaGetSymbolAddress((void**)&pB,  g_B);
    cudaGetSymbolAddress((void**)&px0, g_x0);

    lift_kernel<<< (4 * CC * (NPIX / 4) + 255) / 256, 256 >>> (x, lw, lb);

    const float* cur = px0;
    for (int n = 0; n < 4; n++) {
        int bcast = (n == 0);
        int last  = (n == 3);
        float* nxt = (n & 1) ? pB : pA;

        dft_fwd_kernel <<< 512, 256 >>> (cur, bcast);
        mix_invh_kernel<<< 512, 256 >>> (wr, wi, n);
        finish_kernel  <<< 4096, 128 >>> (cur, nxt, bw, bb, pw, pb, out, n, bcast, last);

        cur = nxt;
    }
}